// round 10
// baseline (speedup 1.0000x reference)
#include <cuda_runtime.h>
#include <cuda_bf16.h>
#include <cstdint>

#define B_SZ 2048
#define K_SZ 64
#define D_SZ 768      // C*E*E
#define F_SZ 64       // CF_FEAT
#define KC   64       // k elements per chunk
#define NCHUNK (D_SZ / KC)   // 12
#define ROWS 128      // GEMM rows per CTA
#define CAP  16       // max candidates per b
#define DELTA 0.006f  // candidate margin (>=15 sigma of cheap-score error)

// ---------------- device scratch ----------------
__device__ float g_Xf[B_SZ * F_SZ];
__device__ int   g_cand[B_SZ * CAP];
__device__ int   g_ccnt[B_SZ];
__device__ float g_rs[B_SZ * CAP];
__device__ __align__(16) __nv_bfloat16 g_BphHi[F_SZ * D_SZ];
__device__ __align__(16) __nv_bfloat16 g_BphLo[F_SZ * D_SZ];
__device__ __align__(16) __nv_bfloat16 g_BthHi[F_SZ * D_SZ];
__device__ __align__(16) __nv_bfloat16 g_BthLo[F_SZ * D_SZ];

// ---------------- helpers ----------------
__device__ __forceinline__ uint32_t smem_u32(const void* p) {
    uint32_t a;
    asm("{ .reg .u64 t; cvta.to.shared.u64 t, %1; cvt.u32.u64 %0, t; }"
        : "=r"(a) : "l"(p));
    return a;
}
#define LDSM4(r, addr) \
    asm volatile("ldmatrix.sync.aligned.m8n8.x4.shared.b16 {%0,%1,%2,%3}, [%4];" \
        : "=r"((r)[0]), "=r"((r)[1]), "=r"((r)[2]), "=r"((r)[3]) : "r"(addr))
#define MMA16816(c, a, b0, b1) \
    asm volatile("mma.sync.aligned.m16n8k16.row.col.f32.bf16.bf16.f32 " \
        "{%0,%1,%2,%3}, {%4,%5,%6,%7}, {%8,%9}, {%0,%1,%2,%3};" \
        : "+f"((c)[0]), "+f"((c)[1]), "+f"((c)[2]), "+f"((c)[3]) \
        : "r"((a)[0]), "r"((a)[1]), "r"((a)[2]), "r"((a)[3]), "r"(b0), "r"(b1))

__device__ __forceinline__ uint32_t pack_hi(float x, float y,
                                            float& lx, float& ly) {
    __nv_bfloat16 hx = __float2bfloat16(x), hy = __float2bfloat16(y);
    lx = x - __bfloat162float(hx);
    ly = y - __bfloat162float(hy);
    return ((uint32_t)__bfloat16_as_ushort(hy) << 16) | __bfloat16_as_ushort(hx);
}
__device__ __forceinline__ uint32_t pack_bf(float x, float y) {
    return ((uint32_t)__bfloat16_as_ushort(__float2bfloat16(y)) << 16)
         | __bfloat16_as_ushort(__float2bfloat16(x));
}

// ---------------- K0: split W's into bf16 hi/lo ----------------
__global__ void k_prep(const float* __restrict__ Wth, const float* __restrict__ Wph) {
    int i = blockIdx.x * 256 + threadIdx.x;
    if (i < F_SZ * D_SZ) {
        float a = Wph[i];
        __nv_bfloat16 h = __float2bfloat16(a);
        g_BphHi[i] = h;
        g_BphLo[i] = __float2bfloat16(a - __bfloat162float(h));
        float b = Wth[i];
        __nv_bfloat16 g = __float2bfloat16(b);
        g_BthHi[i] = g;
        g_BthLo[i] = __float2bfloat16(b - __bfloat162float(g));
    }
}

// ================= x_feat kernel (R6 3-pass path, mode 1 only) =============
#define OFF_AHI   0
#define OFF_ALO   18432
#define OFF_BHI   36864
#define OFF_BLO   46080
#define OFF_XF    55296
#define OFF_BIAS  55808
#define SMEM_BYTES 56064

__global__ __launch_bounds__(256) void k_feat(const float* __restrict__ src,
                                              const float* __restrict__ bias,
                                              int mode) {
    extern __shared__ __align__(16) char sp[];
    const uint32_t sb = smem_u32(sp);
    const int tid = threadIdx.x;
    const int w = tid >> 5, lane = tid & 31;

    const __nv_bfloat16* gBhi = mode ? g_BthHi : g_BphHi;
    const __nv_bfloat16* gBlo = mode ? g_BthLo : g_BphLo;

    if (tid < F_SZ) ((float*)(sp + OFF_BIAS))[tid] = bias[tid];

    const float* Ab = src + (size_t)blockIdx.x * ROWS * D_SZ;

    float4 ar[8];
    uint2 bh[4], bl[4];
#define LOAD_A(t) do {                                                          \
    _Pragma("unroll")                                                           \
    for (int i = 0; i < 8; i++) {                                               \
        int l = tid + 256 * i; int row = l >> 4, c4 = l & 15;                   \
        ar[i] = *(const float4*)(Ab + row * D_SZ + (t) * KC + c4 * 4);          \
    } } while (0)
#define LOAD_B(t) do {                                                          \
    _Pragma("unroll")                                                           \
    for (int i = 0; i < 4; i++) {                                               \
        int l = tid + 256 * i; int row = l >> 4, u = l & 15;                    \
        bh[i] = *(const uint2*)(gBhi + row * D_SZ + (t) * KC + u * 4);          \
        bl[i] = *(const uint2*)(gBlo + row * D_SZ + (t) * KC + u * 4);          \
    } } while (0)

    LOAD_A(0); LOAD_B(0);

    float acc[8][4];
#pragma unroll
    for (int j = 0; j < 8; j++)
#pragma unroll
        for (int q = 0; q < 4; q++) acc[j][q] = 0.f;

    const int m8  = lane & 7;
    const int grp = lane >> 3;
    const uint32_t aoffBase = (uint32_t)((16 * w + (grp & 1) * 8 + m8) * 144
                                         + ((grp >> 1) * 8) * 2);
    const uint32_t brow     = (uint32_t)(((grp >> 1) * 8 + m8) * 144);
    const uint32_t bcolg    = (uint32_t)(((grp & 1) * 8) * 2);

#pragma unroll 1
    for (int t = 0; t < NCHUNK; t++) {
#pragma unroll
        for (int i = 0; i < 8; i++) {
            int l = tid + 256 * i; int row = l >> 4, c4 = l & 15;
            float4 v = ar[i];
            float l0, l1, l2, l3;
            uint32_t h01 = pack_hi(v.x, v.y, l0, l1);
            uint32_t h23 = pack_hi(v.z, v.w, l2, l3);
            uint32_t q01 = pack_bf(l0, l1);
            uint32_t q23 = pack_bf(l2, l3);
            uint32_t off = (uint32_t)(row * 144 + c4 * 8);
            *(uint2*)(sp + OFF_AHI + off) = make_uint2(h01, h23);
            *(uint2*)(sp + OFF_ALO + off) = make_uint2(q01, q23);
        }
#pragma unroll
        for (int i = 0; i < 4; i++) {
            int l = tid + 256 * i; int row = l >> 4, u = l & 15;
            uint32_t off = (uint32_t)(row * 144 + u * 8);
            *(uint2*)(sp + OFF_BHI + off) = bh[i];
            *(uint2*)(sp + OFF_BLO + off) = bl[i];
        }
        __syncthreads();

        if (t + 1 < NCHUNK) { LOAD_A(t + 1); LOAD_B(t + 1); }

#pragma unroll
        for (int ks = 0; ks < 4; ks++) {
            uint32_t ah[4], al[4];
            uint32_t aoff = aoffBase + (uint32_t)(ks * 32);
            LDSM4(ah, sb + OFF_AHI + aoff);
            LDSM4(al, sb + OFF_ALO + aoff);
#pragma unroll
            for (int tp = 0; tp < 4; tp++) {
                uint32_t bhr[4], blr[4];
                uint32_t boff = (uint32_t)(tp * 16 * 144) + brow
                              + bcolg + (uint32_t)(ks * 32);
                LDSM4(bhr, sb + OFF_BHI + boff);
                LDSM4(blr, sb + OFF_BLO + boff);
                MMA16816(acc[2 * tp],     ah, bhr[0], bhr[1]);
                MMA16816(acc[2 * tp + 1], ah, bhr[2], bhr[3]);
                MMA16816(acc[2 * tp],     ah, blr[0], blr[1]);
                MMA16816(acc[2 * tp + 1], ah, blr[2], blr[3]);
                MMA16816(acc[2 * tp],     al, bhr[0], bhr[1]);
                MMA16816(acc[2 * tp + 1], al, bhr[2], bhr[3]);
            }
        }
        __syncthreads();
    }

    const int qr = lane >> 2, qc = lane & 3;
    const float* bs = (const float*)(sp + OFF_BIAS);
#pragma unroll
    for (int h = 0; h < 2; h++) {
        const int row = 16 * w + h * 8 + qr;
        float n2 = 0.f;
#pragma unroll
        for (int j = 0; j < 8; j++) {
            int c = j * 8 + qc * 2;
            float v0 = acc[j][h * 2 + 0] + bs[c];
            float v1 = acc[j][h * 2 + 1] + bs[c + 1];
            n2 = fmaf(v0, v0, n2); n2 = fmaf(v1, v1, n2);
        }
        n2 += __shfl_xor_sync(0xffffffffu, n2, 1);
        n2 += __shfl_xor_sync(0xffffffffu, n2, 2);
        float inv = 1.0f / fmaxf(sqrtf(n2), 1e-12f);
        float* o = g_Xf + ((size_t)blockIdx.x * 128 + row) * 64;
#pragma unroll
        for (int j = 0; j < 8; j++) {
            int c = j * 8 + qc * 2;
            o[c]     = (acc[j][h * 2 + 0] + bs[c]) * inv;
            o[c + 1] = (acc[j][h * 2 + 1] + bs[c + 1]) * inv;
        }
    }
}

// ================= Stage 1: single-pass bf16 score + candidate select ======
// B (Wphi-hi) fully resident in smem (row stride 1552B), A streamed from gmem
// directly in fragment layout. No mainloop syncs.
#define BSTR 1552
#define SOFF_B    0
#define SOFF_SC   99328
#define SOFF_XF   99840
#define SOFF_BIAS 100352
#define SC_SMEM   100608

__global__ __launch_bounds__(256, 2) void k_score(
    const float* __restrict__ p_im, const float* __restrict__ bphi)
{
    extern __shared__ __align__(16) char sp[];
    const uint32_t sb = smem_u32(sp);
    const int tid = threadIdx.x;
    const int w = tid >> 5, lane = tid & 31;
    const int qr = lane >> 2, qc = lane & 3;
    const int m8 = lane & 7, grp = lane >> 3;

    // ---- load B (64 f-rows x 768 d bf16) into padded smem ----
#pragma unroll
    for (int i = 0; i < 24; i++) {
        int idx = tid + 256 * i;        // 16B units: 64 rows * 96
        int f = idx / 96, c = idx % 96;
        *(uint4*)(sp + SOFF_B + f * BSTR + c * 16) =
            *(const uint4*)((const char*)g_BphHi + f * 1536 + c * 16);
    }
    if (tid < F_SZ) ((float*)(sp + SOFF_BIAS))[tid] = bphi[tid];
    if (tid < 128)
        ((float*)(sp + SOFF_XF))[tid] = g_Xf[(size_t)blockIdx.x * 128 + tid];
    __syncthreads();

    const float* Arow0 = p_im + (size_t)blockIdx.x * ROWS * D_SZ
                       + (16 * w + qr) * D_SZ + 2 * qc;

    float2 pf[16];
#define LOAD_AF(t) do {                                                     \
    const float* bp = Arow0 + (t) * KC;                                     \
    _Pragma("unroll")                                                       \
    for (int ks = 0; ks < 4; ks++) {                                        \
        pf[ks * 4 + 0] = *(const float2*)(bp + ks * 16);                    \
        pf[ks * 4 + 1] = *(const float2*)(bp + ks * 16 + 8 * D_SZ);         \
        pf[ks * 4 + 2] = *(const float2*)(bp + ks * 16 + 8);                \
        pf[ks * 4 + 3] = *(const float2*)(bp + ks * 16 + 8 * D_SZ + 8);     \
    } } while (0)

    LOAD_AF(0);

    float acc[8][4];
#pragma unroll
    for (int j = 0; j < 8; j++)
#pragma unroll
        for (int q = 0; q < 4; q++) acc[j][q] = 0.f;

    const uint32_t bbase = sb + SOFF_B
        + (uint32_t)(((grp >> 1) * 8 + m8) * BSTR + (grp & 1) * 16);

#pragma unroll 1
    for (int t = 0; t < NCHUNK; t++) {
        uint32_t af[16];
#pragma unroll
        for (int i = 0; i < 16; i++) {
            __nv_bfloat162 h = __float22bfloat162_rn(make_float2(pf[i].x, pf[i].y));
            af[i] = *(uint32_t*)&h;
        }
        if (t + 1 < NCHUNK) LOAD_AF(t + 1);
#pragma unroll
        for (int ks = 0; ks < 4; ks++) {
#pragma unroll
            for (int tp = 0; tp < 4; tp++) {
                uint32_t bh[4];
                uint32_t boff = bbase + (uint32_t)(tp * 16 * BSTR + ks * 32 + t * 128);
                LDSM4(bh, boff);
                MMA16816(acc[2 * tp],     &af[ks * 4], bh[0], bh[1]);
                MMA16816(acc[2 * tp + 1], &af[ks * 4], bh[2], bh[3]);
            }
        }
    }

    // ---- epilogue: bias + norm + dot -> cheap scores in smem ----
    const float* bs = (const float*)(sp + SOFF_BIAS);
    float* sc = (float*)(sp + SOFF_SC);
#pragma unroll
    for (int h = 0; h < 2; h++) {
        const int row = 16 * w + h * 8 + qr;
        const float* xf = (const float*)(sp + SOFF_XF) + (row >> 6) * 64;
        float n2 = 0.f, dp = 0.f;
#pragma unroll
        for (int j = 0; j < 8; j++) {
            int c = j * 8 + qc * 2;
            float v0 = acc[j][h * 2 + 0] + bs[c];
            float v1 = acc[j][h * 2 + 1] + bs[c + 1];
            n2 = fmaf(v0, v0, n2); n2 = fmaf(v1, v1, n2);
            dp = fmaf(xf[c], v0, dp); dp = fmaf(xf[c + 1], v1, dp);
        }
        n2 += __shfl_xor_sync(0xffffffffu, n2, 1);
        n2 += __shfl_xor_sync(0xffffffffu, n2, 2);
        dp += __shfl_xor_sync(0xffffffffu, dp, 1);
        dp += __shfl_xor_sync(0xffffffffu, dp, 2);
        if (qc == 0) sc[row] = dp / fmaxf(sqrtf(n2), 1e-12f);
    }
    __syncthreads();

    // ---- candidate selection: warp 0 -> b0, warp 1 -> b1 ----
    if (w < 2) {
        const int b = blockIdx.x * 2 + w;
        float s0 = sc[w * 64 + lane];
        float s1 = sc[w * 64 + 32 + lane];
        float m = fmaxf(s0, s1);
#pragma unroll
        for (int o = 16; o; o >>= 1)
            m = fmaxf(m, __shfl_xor_sync(0xffffffffu, m, o));
        float thr = m - DELTA;
        unsigned b0m = __ballot_sync(0xffffffffu, s0 > thr);
        unsigned b1m = __ballot_sync(0xffffffffu, s1 > thr);
        int c0 = __popc(b0m);
        int cnt = c0 + __popc(b1m);
        unsigned lt = (1u << lane) - 1u;
        if (lane == 0) g_ccnt[b] = min(cnt, CAP);
        if (s0 > thr) {
            int slot = __popc(b0m & lt);
            if (slot < CAP) g_cand[b * CAP + slot] = lane;
        }
        if (s1 > thr) {
            int slot = c0 + __popc(b1m & lt);
            if (slot < CAP) g_cand[b * CAP + slot] = 32 + lane;
        }
    }
}

// ================= Stage 2: fp32 refinement of candidates ==================
#define RB 16
#define ROFF_WV 0                      // 192*64 float4 = 196608
#define ROFF_PS 196608                 // 4*768*4     = 12288
#define ROFF_BPH 208896                // 256
#define ROFF_LB  209152                // 256 int
#define ROFF_LK  210176
#define ROFF_LS  211200
#define ROFF_CNT 212224                // RB int
#define ROFF_BASE 212288               // RB int
#define ROFF_N   212352                // int
#define ROFF_RED 212356                // 16 floats (+pad)
#define RF_SMEM  212432

__global__ __launch_bounds__(256, 1) void k_refine(
    const float* __restrict__ p_im, const float* __restrict__ Wphi,
    const float* __restrict__ bphi)
{
    extern __shared__ __align__(16) char sp[];
    const int tid = threadIdx.x;
    const int b0 = blockIdx.x * RB;
    float4* WV = (float4*)(sp + ROFF_WV);
    float4* PS = (float4*)(sp + ROFF_PS);
    float*  BPH = (float*)(sp + ROFF_BPH);
    int* LB = (int*)(sp + ROFF_LB);
    int* LK = (int*)(sp + ROFF_LK);
    int* LS = (int*)(sp + ROFF_LS);
    int* CNT = (int*)(sp + ROFF_CNT);
    int* BASE = (int*)(sp + ROFF_BASE);
    int* NN = (int*)(sp + ROFF_N);
    float* RED = (float*)(sp + ROFF_RED);

    // stage Wphi: WV[dg*64 + f] = W[f][4dg..4dg+3]
    for (int i = tid; i < 64 * 192; i += 256) {
        int f = i & 63, dg = i >> 6;
        WV[dg * 64 + f] = *(const float4*)(Wphi + f * D_SZ + dg * 4);
    }
    if (tid < F_SZ) BPH[tid] = bphi[tid];
    if (tid < RB) CNT[tid] = g_ccnt[b0 + tid];
    __syncthreads();
    if (tid == 0) {
        int n = 0;
        for (int j = 0; j < RB; j++) { BASE[j] = n; n += CNT[j]; }
        NN[0] = n;
    }
    __syncthreads();
    if (tid < RB) {
        int c = CNT[tid], base = BASE[tid];
        for (int j = 0; j < c; j++) {
            LB[base + j] = tid;
            LS[base + j] = j;
            LK[base + j] = g_cand[(b0 + tid) * CAP + j];
        }
    }
    __syncthreads();
    const int N = NN[0];

    for (int r = 0; r < N; r += 4) {
        // stage up to 4 p_im rows
        for (int i = tid; i < 4 * D_SZ; i += 256) {
            int c = i / D_SZ;
            if (r + c < N) {
                int row = (b0 + LB[r + c]) * K_SZ + LK[r + c];
                ((float*)PS)[i] = p_im[(size_t)row * D_SZ + (i - c * D_SZ)];
            }
        }
        __syncthreads();

        int cand = tid >> 6, f = tid & 63, ci = r + cand;
        float nn = 0.f, dd = 0.f;
        if (ci < N) {
            float a = 0.f;
#pragma unroll 4
            for (int g = 0; g < 192; g++) {
                float4 wv = WV[g * 64 + f];
                float4 pv = PS[cand * 192 + g];
                a = fmaf(wv.x, pv.x, a); a = fmaf(wv.y, pv.y, a);
                a = fmaf(wv.z, pv.z, a); a = fmaf(wv.w, pv.w, a);
            }
            float v = a + BPH[f];
            nn = v * v;
            dd = v * g_Xf[(size_t)(b0 + LB[ci]) * 64 + f];
        }
#pragma unroll
        for (int o = 16; o; o >>= 1) {
            nn += __shfl_xor_sync(0xffffffffu, nn, o);
            dd += __shfl_xor_sync(0xffffffffu, dd, o);
        }
        int wid = tid >> 5;
        if ((tid & 31) == 0) { RED[wid * 2] = nn; RED[wid * 2 + 1] = dd; }
        __syncthreads();
        if (tid < 4 && r + tid < N) {
            float n2 = RED[tid * 4 + 0] + RED[tid * 4 + 2];
            float dp = RED[tid * 4 + 1] + RED[tid * 4 + 3];
            g_rs[(b0 + LB[r + tid]) * CAP + LS[r + tid]] =
                dp / fmaxf(sqrtf(n2), 1e-12f);
        }
        __syncthreads();
    }
}

// ================= K3: switch + candidate softmax + sparse sum + mix =======
__global__ __launch_bounds__(256) void k_output(
    const float* __restrict__ x, const float* __restrict__ p,
    const float* __restrict__ Wg, const float* __restrict__ bg,
    const float* __restrict__ Wo, const float* __restrict__ bo,
    const float* __restrict__ sig_scale, const float* __restrict__ sig_shift,
    float* __restrict__ out)
{
    __shared__ float wsm[CAP];
    __shared__ int   kk[CAP];
    __shared__ int   s_cnt;
    __shared__ float s_sw;
    const int b = blockIdx.x, tid = threadIdx.x;

    if (tid == 0) s_cnt = g_ccnt[b];
    __syncthreads();
    const int cnt = s_cnt;
    if (tid < cnt) {
        wsm[tid] = g_rs[b * CAP + tid];
        kk[tid]  = g_cand[b * CAP + tid];
    }
    __syncthreads();
    if (tid == 0) {
        float m = -1e30f;
        for (int i = 0; i < cnt; i++) m = fmaxf(m, wsm[i]);
        float z = m * sig_scale[0] + sig_shift[0];
        s_sw = 1.0f / (1.0f + expf(-z));
        float s = 0.f;
        for (int i = 0; i < cnt; i++) {
            float e = expf(1048576.0f * (wsm[i] - m));
            wsm[i] = e; s += e;
        }
        float inv = 1.0f / s;
        for (int i = 0; i < cnt; i++) wsm[i] *= inv;
    }
    __syncthreads();

    const float sw = s_sw;
    float acc0 = 0.f, acc1 = 0.f, acc2 = 0.f;
    const float* pb = p + (size_t)b * K_SZ * D_SZ;
    for (int i = 0; i < cnt; i++) {
        float wk = wsm[i];
        if (wk > 1e-12f) {
            const float* pr = pb + kk[i] * D_SZ;
            acc0 = fmaf(wk, pr[tid],       acc0);
            acc1 = fmaf(wk, pr[tid + 256], acc1);
            acc2 = fmaf(wk, pr[tid + 512], acc2);
        }
    }

    float mx0 = fmaf(Wg[0], acc0, fmaf(Wg[1], acc1, fmaf(Wg[2], acc2, bg[0])));
    float mx1 = fmaf(Wg[3], acc0, fmaf(Wg[4], acc1, fmaf(Wg[5], acc2, bg[1])));
    float mx2 = fmaf(Wg[6], acc0, fmaf(Wg[7], acc1, fmaf(Wg[8], acc2, bg[2])));

    const float* xb = x + (size_t)b * D_SZ;
    float* ob = out + (size_t)b * D_SZ;
#pragma unroll
    for (int o = 0; o < 3; o++) {
        float pa = fmaf(Wo[o * 3 + 0], mx0,
                   fmaf(Wo[o * 3 + 1], mx1,
                   fmaf(Wo[o * 3 + 2], mx2, bo[o])));
        float xv = xb[o * 256 + tid];
        ob[o * 256 + tid] = xv * (1.0f - sw) + pa * sw;
    }
}

// ---------------- launch ----------------
extern "C" void kernel_launch(void* const* d_in, const int* in_sizes, int n_in,
                              void* d_out, int out_size) {
    const float* x         = (const float*)d_in[0];
    const float* p         = (const float*)d_in[1];
    const float* x_im      = (const float*)d_in[2];
    const float* p_im      = (const float*)d_in[3];
    const float* Wtheta    = (const float*)d_in[4];
    const float* btheta    = (const float*)d_in[5];
    const float* Wphi      = (const float*)d_in[6];
    const float* bphi      = (const float*)d_in[7];
    const float* Wg        = (const float*)d_in[8];
    const float* bg        = (const float*)d_in[9];
    const float* Wo        = (const float*)d_in[10];
    const float* bo        = (const float*)d_in[11];
    const float* sig_scale = (const float*)d_in[12];
    const float* sig_shift = (const float*)d_in[13];
    float* out = (float*)d_out;

    static int s_attr_done = 0;
    if (!s_attr_done) {
        cudaFuncSetAttribute(k_feat, cudaFuncAttributeMaxDynamicSharedMemorySize,
                             SMEM_BYTES);
        cudaFuncSetAttribute(k_score, cudaFuncAttributeMaxDynamicSharedMemorySize,
                             SC_SMEM);
        cudaFuncSetAttribute(k_refine, cudaFuncAttributeMaxDynamicSharedMemorySize,
                             RF_SMEM);
        s_attr_done = 1;
    }

    k_prep<<<(F_SZ * D_SZ + 255) / 256, 256>>>(Wtheta, Wphi);
    k_feat<<<B_SZ / 128, 256, SMEM_BYTES>>>(x_im, btheta, 1);   // x_feat (3-pass)
    k_score<<<B_SZ * K_SZ / 128, 256, SC_SMEM>>>(p_im, bphi);   // cheap scores + cands
    k_refine<<<B_SZ / RB, 256, RF_SMEM>>>(p_im, Wphi, bphi);    // fp32 refine
    k_output<<<B_SZ, 256>>>(x, p, Wg, bg, Wo, bo, sig_scale, sig_shift, out);
}

// round 11
// speedup vs baseline: 1.1197x; 1.1197x over previous
#include <cuda_runtime.h>
#include <cuda_bf16.h>
#include <cstdint>

#define B_SZ 2048
#define K_SZ 64
#define D_SZ 768      // C*E*E
#define F_SZ 64       // CF_FEAT
#define KC   64       // k elements per chunk
#define NCHUNK (D_SZ / KC)   // 12
#define ROWS 128      // GEMM rows per CTA (stage 1)
#define CAP  16       // max candidates per b
#define DELTA 0.006f  // candidate margin
#define LISTMAX (B_SZ * CAP)

// ---------------- device scratch ----------------
__device__ float g_Xf[B_SZ * F_SZ];
__device__ int   g_cand[B_SZ * CAP];
__device__ int   g_ccnt[B_SZ];
__device__ float g_rs[B_SZ * CAP];
__device__ int   g_ncand;
__device__ int   g_list_gi[LISTMAX];
__device__ int   g_list_row[LISTMAX];
__device__ __align__(16) __nv_bfloat16 g_BphHi[F_SZ * D_SZ];
__device__ __align__(16) __nv_bfloat16 g_BphLo[F_SZ * D_SZ];
__device__ __align__(16) __nv_bfloat16 g_BthHi[F_SZ * D_SZ];
__device__ __align__(16) __nv_bfloat16 g_BthLo[F_SZ * D_SZ];

// ---------------- helpers ----------------
__device__ __forceinline__ uint32_t smem_u32(const void* p) {
    uint32_t a;
    asm("{ .reg .u64 t; cvta.to.shared.u64 t, %1; cvt.u32.u64 %0, t; }"
        : "=r"(a) : "l"(p));
    return a;
}
#define LDSM4(r, addr) \
    asm volatile("ldmatrix.sync.aligned.m8n8.x4.shared.b16 {%0,%1,%2,%3}, [%4];" \
        : "=r"((r)[0]), "=r"((r)[1]), "=r"((r)[2]), "=r"((r)[3]) : "r"(addr))
#define MMA16816(c, a, b0, b1) \
    asm volatile("mma.sync.aligned.m16n8k16.row.col.f32.bf16.bf16.f32 " \
        "{%0,%1,%2,%3}, {%4,%5,%6,%7}, {%8,%9}, {%0,%1,%2,%3};" \
        : "+f"((c)[0]), "+f"((c)[1]), "+f"((c)[2]), "+f"((c)[3]) \
        : "r"((a)[0]), "r"((a)[1]), "r"((a)[2]), "r"((a)[3]), "r"(b0), "r"(b1))

__device__ __forceinline__ uint32_t pack_hi(float x, float y,
                                            float& lx, float& ly) {
    __nv_bfloat16 hx = __float2bfloat16(x), hy = __float2bfloat16(y);
    lx = x - __bfloat162float(hx);
    ly = y - __bfloat162float(hy);
    return ((uint32_t)__bfloat16_as_ushort(hy) << 16) | __bfloat16_as_ushort(hx);
}
__device__ __forceinline__ uint32_t pack_bf(float x, float y) {
    return ((uint32_t)__bfloat16_as_ushort(__float2bfloat16(y)) << 16)
         | __bfloat16_as_ushort(__float2bfloat16(x));
}

// ---------------- K0: split W's into bf16 hi/lo + reset counter ------------
__global__ void k_prep(const float* __restrict__ Wth, const float* __restrict__ Wph) {
    int i = blockIdx.x * 256 + threadIdx.x;
    if (i == 0) g_ncand = 0;
    if (i < F_SZ * D_SZ) {
        float a = Wph[i];
        __nv_bfloat16 h = __float2bfloat16(a);
        g_BphHi[i] = h;
        g_BphLo[i] = __float2bfloat16(a - __bfloat162float(h));
        float b = Wth[i];
        __nv_bfloat16 g = __float2bfloat16(b);
        g_BthHi[i] = g;
        g_BthLo[i] = __float2bfloat16(b - __bfloat162float(g));
    }
}

// ================= x_feat kernel (3-pass, 16 CTAs) ========================
#define OFF_AHI   0
#define OFF_ALO   18432
#define OFF_BHI   36864
#define OFF_BLO   46080
#define OFF_XF    55296
#define OFF_BIAS  55808
#define SMEM_BYTES 56064

__global__ __launch_bounds__(256) void k_feat(const float* __restrict__ src,
                                              const float* __restrict__ bias) {
    extern __shared__ __align__(16) char sp[];
    const uint32_t sb = smem_u32(sp);
    const int tid = threadIdx.x;
    const int w = tid >> 5, lane = tid & 31;

    const __nv_bfloat16* gBhi = g_BthHi;
    const __nv_bfloat16* gBlo = g_BthLo;

    if (tid < F_SZ) ((float*)(sp + OFF_BIAS))[tid] = bias[tid];

    const float* Ab = src + (size_t)blockIdx.x * ROWS * D_SZ;

    float4 ar[8];
    uint2 bh[4], bl[4];
#define LOAD_A(t) do {                                                          \
    _Pragma("unroll")                                                           \
    for (int i = 0; i < 8; i++) {                                               \
        int l = tid + 256 * i; int row = l >> 4, c4 = l & 15;                   \
        ar[i] = *(const float4*)(Ab + row * D_SZ + (t) * KC + c4 * 4);          \
    } } while (0)
#define LOAD_B(t) do {                                                          \
    _Pragma("unroll")                                                           \
    for (int i = 0; i < 4; i++) {                                               \
        int l = tid + 256 * i; int row = l >> 4, u = l & 15;                    \
        bh[i] = *(const uint2*)(gBhi + row * D_SZ + (t) * KC + u * 4);          \
        bl[i] = *(const uint2*)(gBlo + row * D_SZ + (t) * KC + u * 4);          \
    } } while (0)

    LOAD_A(0); LOAD_B(0);

    float acc[8][4];
#pragma unroll
    for (int j = 0; j < 8; j++)
#pragma unroll
        for (int q = 0; q < 4; q++) acc[j][q] = 0.f;

    const int m8  = lane & 7;
    const int grp = lane >> 3;
    const uint32_t aoffBase = (uint32_t)((16 * w + (grp & 1) * 8 + m8) * 144
                                         + ((grp >> 1) * 8) * 2);
    const uint32_t brow     = (uint32_t)(((grp >> 1) * 8 + m8) * 144);
    const uint32_t bcolg    = (uint32_t)(((grp & 1) * 8) * 2);

#pragma unroll 1
    for (int t = 0; t < NCHUNK; t++) {
#pragma unroll
        for (int i = 0; i < 8; i++) {
            int l = tid + 256 * i; int row = l >> 4, c4 = l & 15;
            float4 v = ar[i];
            float l0, l1, l2, l3;
            uint32_t h01 = pack_hi(v.x, v.y, l0, l1);
            uint32_t h23 = pack_hi(v.z, v.w, l2, l3);
            uint32_t q01 = pack_bf(l0, l1);
            uint32_t q23 = pack_bf(l2, l3);
            uint32_t off = (uint32_t)(row * 144 + c4 * 8);
            *(uint2*)(sp + OFF_AHI + off) = make_uint2(h01, h23);
            *(uint2*)(sp + OFF_ALO + off) = make_uint2(q01, q23);
        }
#pragma unroll
        for (int i = 0; i < 4; i++) {
            int l = tid + 256 * i; int row = l >> 4, u = l & 15;
            uint32_t off = (uint32_t)(row * 144 + u * 8);
            *(uint2*)(sp + OFF_BHI + off) = bh[i];
            *(uint2*)(sp + OFF_BLO + off) = bl[i];
        }
        __syncthreads();

        if (t + 1 < NCHUNK) { LOAD_A(t + 1); LOAD_B(t + 1); }

#pragma unroll
        for (int ks = 0; ks < 4; ks++) {
            uint32_t ah[4], al[4];
            uint32_t aoff = aoffBase + (uint32_t)(ks * 32);
            LDSM4(ah, sb + OFF_AHI + aoff);
            LDSM4(al, sb + OFF_ALO + aoff);
#pragma unroll
            for (int tp = 0; tp < 4; tp++) {
                uint32_t bhr[4], blr[4];
                uint32_t boff = (uint32_t)(tp * 16 * 144) + brow
                              + bcolg + (uint32_t)(ks * 32);
                LDSM4(bhr, sb + OFF_BHI + boff);
                LDSM4(blr, sb + OFF_BLO + boff);
                MMA16816(acc[2 * tp],     ah, bhr[0], bhr[1]);
                MMA16816(acc[2 * tp + 1], ah, bhr[2], bhr[3]);
                MMA16816(acc[2 * tp],     ah, blr[0], blr[1]);
                MMA16816(acc[2 * tp + 1], ah, blr[2], blr[3]);
                MMA16816(acc[2 * tp],     al, bhr[0], bhr[1]);
                MMA16816(acc[2 * tp + 1], al, bhr[2], bhr[3]);
            }
        }
        __syncthreads();
    }

    const int qr = lane >> 2, qc = lane & 3;
    const float* bs = (const float*)(sp + OFF_BIAS);
#pragma unroll
    for (int h = 0; h < 2; h++) {
        const int row = 16 * w + h * 8 + qr;
        float n2 = 0.f;
#pragma unroll
        for (int j = 0; j < 8; j++) {
            int c = j * 8 + qc * 2;
            float v0 = acc[j][h * 2 + 0] + bs[c];
            float v1 = acc[j][h * 2 + 1] + bs[c + 1];
            n2 = fmaf(v0, v0, n2); n2 = fmaf(v1, v1, n2);
        }
        n2 += __shfl_xor_sync(0xffffffffu, n2, 1);
        n2 += __shfl_xor_sync(0xffffffffu, n2, 2);
        float inv = 1.0f / fmaxf(sqrtf(n2), 1e-12f);
        float* o = g_Xf + ((size_t)blockIdx.x * 128 + row) * 64;
#pragma unroll
        for (int j = 0; j < 8; j++) {
            int c = j * 8 + qc * 2;
            o[c]     = (acc[j][h * 2 + 0] + bs[c]) * inv;
            o[c + 1] = (acc[j][h * 2 + 1] + bs[c + 1]) * inv;
        }
    }
}

// ================= Stage 1: single-pass staged-A score + candidates ========
// smem (static): AHI[128][72]bf16, BHI[64][72]bf16, sc[128], xf[128], bias[64]
#define S2_AHI   0
#define S2_BHI   18432
#define S2_SC    27648
#define S2_XF    28160
#define S2_BIAS  28672
#define S2_BYTES 28928

__global__ __launch_bounds__(256) void k_score2(
    const float* __restrict__ p_im, const float* __restrict__ bphi)
{
    __shared__ __align__(16) char sp[S2_BYTES];
    const uint32_t sb = smem_u32(sp);
    const int tid = threadIdx.x;
    const int w = tid >> 5, lane = tid & 31;

    if (tid < F_SZ) ((float*)(sp + S2_BIAS))[tid] = bphi[tid];
    if (tid < 128)
        ((float*)(sp + S2_XF))[tid] = g_Xf[(size_t)blockIdx.x * 128 + tid];

    const float* Ab = p_im + (size_t)blockIdx.x * ROWS * D_SZ;

    float4 ar[8];
    uint2 bh[4];
#define S2_LOAD_A(t) do {                                                       \
    _Pragma("unroll")                                                           \
    for (int i = 0; i < 8; i++) {                                               \
        int l = tid + 256 * i; int row = l >> 4, c4 = l & 15;                   \
        ar[i] = *(const float4*)(Ab + row * D_SZ + (t) * KC + c4 * 4);          \
    } } while (0)
#define S2_LOAD_B(t) do {                                                       \
    _Pragma("unroll")                                                           \
    for (int i = 0; i < 4; i++) {                                               \
        int l = tid + 256 * i; int row = l >> 4, u = l & 15;                    \
        bh[i] = *(const uint2*)(g_BphHi + row * D_SZ + (t) * KC + u * 4);       \
    } } while (0)

    S2_LOAD_A(0); S2_LOAD_B(0);

    float acc[8][4];
#pragma unroll
    for (int j = 0; j < 8; j++)
#pragma unroll
        for (int q = 0; q < 4; q++) acc[j][q] = 0.f;

    const int m8  = lane & 7;
    const int grp = lane >> 3;
    const uint32_t aoffBase = (uint32_t)((16 * w + (grp & 1) * 8 + m8) * 144
                                         + ((grp >> 1) * 8) * 2);
    const uint32_t brow     = (uint32_t)(((grp >> 1) * 8 + m8) * 144);
    const uint32_t bcolg    = (uint32_t)(((grp & 1) * 8) * 2);

#pragma unroll 1
    for (int t = 0; t < NCHUNK; t++) {
#pragma unroll
        for (int i = 0; i < 8; i++) {
            int l = tid + 256 * i; int row = l >> 4, c4 = l & 15;
            float4 v = ar[i];
            uint32_t h01 = pack_bf(v.x, v.y);
            uint32_t h23 = pack_bf(v.z, v.w);
            *(uint2*)(sp + S2_AHI + (uint32_t)(row * 144 + c4 * 8)) =
                make_uint2(h01, h23);
        }
#pragma unroll
        for (int i = 0; i < 4; i++) {
            int l = tid + 256 * i; int row = l >> 4, u = l & 15;
            *(uint2*)(sp + S2_BHI + (uint32_t)(row * 144 + u * 8)) = bh[i];
        }
        __syncthreads();

        if (t + 1 < NCHUNK) { S2_LOAD_A(t + 1); S2_LOAD_B(t + 1); }

#pragma unroll
        for (int ks = 0; ks < 4; ks++) {
            uint32_t ah[4];
            LDSM4(ah, sb + S2_AHI + aoffBase + (uint32_t)(ks * 32));
#pragma unroll
            for (int tp = 0; tp < 4; tp++) {
                uint32_t bhr[4];
                uint32_t boff = (uint32_t)(tp * 16 * 144) + brow
                              + bcolg + (uint32_t)(ks * 32);
                LDSM4(bhr, sb + S2_BHI + boff);
                MMA16816(acc[2 * tp],     ah, bhr[0], bhr[1]);
                MMA16816(acc[2 * tp + 1], ah, bhr[2], bhr[3]);
            }
        }
        __syncthreads();
    }

    // ---- epilogue: bias + norm + dot -> cheap scores ----
    const int qr = lane >> 2, qc = lane & 3;
    const float* bs = (const float*)(sp + S2_BIAS);
    float* sc = (float*)(sp + S2_SC);
#pragma unroll
    for (int h = 0; h < 2; h++) {
        const int row = 16 * w + h * 8 + qr;
        const float* xf = (const float*)(sp + S2_XF) + (row >> 6) * 64;
        float n2 = 0.f, dp = 0.f;
#pragma unroll
        for (int j = 0; j < 8; j++) {
            int c = j * 8 + qc * 2;
            float v0 = acc[j][h * 2 + 0] + bs[c];
            float v1 = acc[j][h * 2 + 1] + bs[c + 1];
            n2 = fmaf(v0, v0, n2); n2 = fmaf(v1, v1, n2);
            dp = fmaf(xf[c], v0, dp); dp = fmaf(xf[c + 1], v1, dp);
        }
        n2 += __shfl_xor_sync(0xffffffffu, n2, 1);
        n2 += __shfl_xor_sync(0xffffffffu, n2, 2);
        dp += __shfl_xor_sync(0xffffffffu, dp, 1);
        dp += __shfl_xor_sync(0xffffffffu, dp, 2);
        if (qc == 0) sc[row] = dp / fmaxf(sqrtf(n2), 1e-12f);
    }
    __syncthreads();

    // ---- candidate selection + global push: warp 0 -> b0, warp 1 -> b1 ----
    if (w < 2) {
        const int b = blockIdx.x * 2 + w;
        float s0 = sc[w * 64 + lane];
        float s1 = sc[w * 64 + 32 + lane];
        float m = fmaxf(s0, s1);
#pragma unroll
        for (int o = 16; o; o >>= 1)
            m = fmaxf(m, __shfl_xor_sync(0xffffffffu, m, o));
        float thr = m - DELTA;
        unsigned b0m = __ballot_sync(0xffffffffu, s0 > thr);
        unsigned b1m = __ballot_sync(0xffffffffu, s1 > thr);
        int c0 = __popc(b0m);
        int cnt = min(c0 + __popc(b1m), CAP);
        unsigned lt = (1u << lane) - 1u;
        int gbase = 0;
        if (lane == 0) {
            g_ccnt[b] = cnt;
            gbase = atomicAdd(&g_ncand, cnt);
        }
        gbase = __shfl_sync(0xffffffffu, gbase, 0);
        if (s0 > thr) {
            int slot = __popc(b0m & lt);
            if (slot < CAP) {
                g_cand[b * CAP + slot] = lane;
                g_list_gi[gbase + slot] = b * CAP + slot;
                g_list_row[gbase + slot] = b * K_SZ + lane;
            }
        }
        if (s1 > thr) {
            int slot = c0 + __popc(b1m & lt);
            if (slot < CAP) {
                g_cand[b * CAP + slot] = 32 + lane;
                g_list_gi[gbase + slot] = b * CAP + slot;
                g_list_row[gbase + slot] = b * K_SZ + 32 + lane;
            }
        }
    }
}

// ================= Stage 2: 3-pass MMA refine on compacted rows ============
// 64 rows/CTA, 128 threads, grid covers LISTMAX; inactive CTAs exit.
#define R3_AHI   0
#define R3_ALO   9216
#define R3_BHI   18432
#define R3_BLO   27648
#define R3_BIAS  36864     // 64 floats
#define R3_GI    37120     // 64 ints
#define R3_BI    37376     // 64 ints
#define R3_PTR   37632     // 64 ptrs (8B)
#define R3_BYTES 38144

__global__ __launch_bounds__(128) void k_refine3(
    const float* __restrict__ p_im, const float* __restrict__ bphi)
{
    __shared__ __align__(16) char sp[R3_BYTES];
    const uint32_t sb = smem_u32(sp);
    const int tid = threadIdx.x;
    const int w = tid >> 5, lane = tid & 31;
    const int N = g_ncand;
    const int base = blockIdx.x * 64;
    if (base >= N) return;

    if (tid < 64) {
        int e = min(base + tid, N - 1);
        int rowid = g_list_row[e];
        ((int*)(sp + R3_GI))[tid] = g_list_gi[e];
        ((int*)(sp + R3_BI))[tid] = rowid >> 6;
        ((const float**)(sp + R3_PTR))[tid] = p_im + (size_t)rowid * D_SZ;
        ((float*)(sp + R3_BIAS))[tid] = bphi[tid];
    }
    __syncthreads();

    const float** rowptr = (const float**)(sp + R3_PTR);

    float4 ar[8];
    uint2 bh[8], bl[8];
#define R3_LOAD_A(t) do {                                                       \
    _Pragma("unroll")                                                           \
    for (int i = 0; i < 8; i++) {                                               \
        int l = tid + 128 * i; int row = l >> 4, c4 = l & 15;                   \
        ar[i] = *(const float4*)(rowptr[row] + (t) * KC + c4 * 4);              \
    } } while (0)
#define R3_LOAD_B(t) do {                                                       \
    _Pragma("unroll")                                                           \
    for (int i = 0; i < 8; i++) {                                               \
        int l = tid + 128 * i; int row = l >> 4, u = l & 15;                    \
        bh[i] = *(const uint2*)(g_BphHi + row * D_SZ + (t) * KC + u * 4);       \
        bl[i] = *(const uint2*)(g_BphLo + row * D_SZ + (t) * KC + u * 4);       \
    } } while (0)

    R3_LOAD_A(0); R3_LOAD_B(0);

    float acc[8][4];
#pragma unroll
    for (int j = 0; j < 8; j++)
#pragma unroll
        for (int q = 0; q < 4; q++) acc[j][q] = 0.f;

    const int m8  = lane & 7;
    const int grp = lane >> 3;
    const uint32_t aoffBase = (uint32_t)((16 * w + (grp & 1) * 8 + m8) * 144
                                         + ((grp >> 1) * 8) * 2);
    const uint32_t brow     = (uint32_t)(((grp >> 1) * 8 + m8) * 144);
    const uint32_t bcolg    = (uint32_t)(((grp & 1) * 8) * 2);

#pragma unroll 1
    for (int t = 0; t < NCHUNK; t++) {
#pragma unroll
        for (int i = 0; i < 8; i++) {
            int l = tid + 128 * i; int row = l >> 4, c4 = l & 15;
            float4 v = ar[i];
            float l0, l1, l2, l3;
            uint32_t h01 = pack_hi(v.x, v.y, l0, l1);
            uint32_t h23 = pack_hi(v.z, v.w, l2, l3);
            uint32_t q01 = pack_bf(l0, l1);
            uint32_t q23 = pack_bf(l2, l3);
            uint32_t off = (uint32_t)(row * 144 + c4 * 8);
            *(uint2*)(sp + R3_AHI + off) = make_uint2(h01, h23);
            *(uint2*)(sp + R3_ALO + off) = make_uint2(q01, q23);
        }
#pragma unroll
        for (int i = 0; i < 8; i++) {
            int l = tid + 128 * i; int row = l >> 4, u = l & 15;
            uint32_t off = (uint32_t)(row * 144 + u * 8);
            *(uint2*)(sp + R3_BHI + off) = bh[i];
            *(uint2*)(sp + R3_BLO + off) = bl[i];
        }
        __syncthreads();

        if (t + 1 < NCHUNK) { R3_LOAD_A(t + 1); R3_LOAD_B(t + 1); }

#pragma unroll
        for (int ks = 0; ks < 4; ks++) {
            uint32_t ah[4], al[4];
            uint32_t aoff = aoffBase + (uint32_t)(ks * 32);
            LDSM4(ah, sb + R3_AHI + aoff);
            LDSM4(al, sb + R3_ALO + aoff);
#pragma unroll
            for (int tp = 0; tp < 4; tp++) {
                uint32_t bhr[4], blr[4];
                uint32_t boff = (uint32_t)(tp * 16 * 144) + brow
                              + bcolg + (uint32_t)(ks * 32);
                LDSM4(bhr, sb + R3_BHI + boff);
                LDSM4(blr, sb + R3_BLO + boff);
                MMA16816(acc[2 * tp],     ah, bhr[0], bhr[1]);
                MMA16816(acc[2 * tp + 1], ah, bhr[2], bhr[3]);
                MMA16816(acc[2 * tp],     ah, blr[0], blr[1]);
                MMA16816(acc[2 * tp + 1], ah, blr[2], blr[3]);
                MMA16816(acc[2 * tp],     al, bhr[0], bhr[1]);
                MMA16816(acc[2 * tp + 1], al, bhr[2], bhr[3]);
            }
        }
        __syncthreads();
    }

    const int qr = lane >> 2, qc = lane & 3;
    const float* bs = (const float*)(sp + R3_BIAS);
#pragma unroll
    for (int h = 0; h < 2; h++) {
        const int row = 16 * w + h * 8 + qr;
        const int b = ((const int*)(sp + R3_BI))[row];
        const float* xf = g_Xf + (size_t)b * 64;
        float n2 = 0.f, dp = 0.f;
#pragma unroll
        for (int j = 0; j < 8; j++) {
            int c = j * 8 + qc * 2;
            float v0 = acc[j][h * 2 + 0] + bs[c];
            float v1 = acc[j][h * 2 + 1] + bs[c + 1];
            n2 = fmaf(v0, v0, n2); n2 = fmaf(v1, v1, n2);
            dp = fmaf(xf[c], v0, dp); dp = fmaf(xf[c + 1], v1, dp);
        }
        n2 += __shfl_xor_sync(0xffffffffu, n2, 1);
        n2 += __shfl_xor_sync(0xffffffffu, n2, 2);
        dp += __shfl_xor_sync(0xffffffffu, dp, 1);
        dp += __shfl_xor_sync(0xffffffffu, dp, 2);
        if (qc == 0 && base + row < N)
            g_rs[((const int*)(sp + R3_GI))[row]] = dp / fmaxf(sqrtf(n2), 1e-12f);
    }
}

// ================= K3: switch + candidate softmax + sparse sum + mix =======
__global__ __launch_bounds__(256) void k_output(
    const float* __restrict__ x, const float* __restrict__ p,
    const float* __restrict__ Wg, const float* __restrict__ bg,
    const float* __restrict__ Wo, const float* __restrict__ bo,
    const float* __restrict__ sig_scale, const float* __restrict__ sig_shift,
    float* __restrict__ out)
{
    __shared__ float wsm[CAP];
    __shared__ int   kk[CAP];
    __shared__ int   s_cnt;
    __shared__ float s_sw;
    const int b = blockIdx.x, tid = threadIdx.x;

    // hoist x loads to overlap latency under the softmax prep
    const float* xb = x + (size_t)b * D_SZ;
    float xv0 = xb[tid], xv1 = xb[tid + 256], xv2 = xb[tid + 512];

    if (tid == 0) s_cnt = g_ccnt[b];
    __syncthreads();
    const int cnt = s_cnt;
    if (tid < cnt) {
        wsm[tid] = g_rs[b * CAP + tid];
        kk[tid]  = g_cand[b * CAP + tid];
    }
    __syncthreads();
    if (tid == 0) {
        float m = -1e30f;
        for (int i = 0; i < cnt; i++) m = fmaxf(m, wsm[i]);
        float z = m * sig_scale[0] + sig_shift[0];
        s_sw = 1.0f / (1.0f + expf(-z));
        float s = 0.f;
        for (int i = 0; i < cnt; i++) {
            float e = expf(1048576.0f * (wsm[i] - m));
            wsm[i] = e; s += e;
        }
        float inv = 1.0f / s;
        for (int i = 0; i < cnt; i++) wsm[i] *= inv;
    }
    __syncthreads();

    const float sw = s_sw;
    float acc0 = 0.f, acc1 = 0.f, acc2 = 0.f;
    const float* pb = p + (size_t)b * K_SZ * D_SZ;
    for (int i = 0; i < cnt; i++) {
        float wk = wsm[i];
        if (wk > 1e-12f) {
            const float* pr = pb + kk[i] * D_SZ;
            acc0 = fmaf(wk, pr[tid],       acc0);
            acc1 = fmaf(wk, pr[tid + 256], acc1);
            acc2 = fmaf(wk, pr[tid + 512], acc2);
        }
    }

    float mx0 = fmaf(Wg[0], acc0, fmaf(Wg[1], acc1, fmaf(Wg[2], acc2, bg[0])));
    float mx1 = fmaf(Wg[3], acc0, fmaf(Wg[4], acc1, fmaf(Wg[5], acc2, bg[1])));
    float mx2 = fmaf(Wg[6], acc0, fmaf(Wg[7], acc1, fmaf(Wg[8], acc2, bg[2])));

    float* ob = out + (size_t)b * D_SZ;
    float pa0 = fmaf(Wo[0], mx0, fmaf(Wo[1], mx1, fmaf(Wo[2], mx2, bo[0])));
    float pa1 = fmaf(Wo[3], mx0, fmaf(Wo[4], mx1, fmaf(Wo[5], mx2, bo[1])));
    float pa2 = fmaf(Wo[6], mx0, fmaf(Wo[7], mx1, fmaf(Wo[8], mx2, bo[2])));
    ob[tid]       = xv0 * (1.0f - sw) + pa0 * sw;
    ob[tid + 256] = xv1 * (1.0f - sw) + pa1 * sw;
    ob[tid + 512] = xv2 * (1.0f - sw) + pa2 * sw;
}

// ---------------- launch ----------------
extern "C" void kernel_launch(void* const* d_in, const int* in_sizes, int n_in,
                              void* d_out, int out_size) {
    const float* x         = (const float*)d_in[0];
    const float* p         = (const float*)d_in[1];
    const float* x_im      = (const float*)d_in[2];
    const float* p_im      = (const float*)d_in[3];
    const float* Wtheta    = (const float*)d_in[4];
    const float* btheta    = (const float*)d_in[5];
    const float* Wphi      = (const float*)d_in[6];
    const float* bphi      = (const float*)d_in[7];
    const float* Wg        = (const float*)d_in[8];
    const float* bg        = (const float*)d_in[9];
    const float* Wo        = (const float*)d_in[10];
    const float* bo        = (const float*)d_in[11];
    const float* sig_scale = (const float*)d_in[12];
    const float* sig_shift = (const float*)d_in[13];
    float* out = (float*)d_out;

    static int s_attr_done = 0;
    if (!s_attr_done) {
        cudaFuncSetAttribute(k_feat, cudaFuncAttributeMaxDynamicSharedMemorySize,
                             SMEM_BYTES);
        s_attr_done = 1;
    }

    k_prep<<<(F_SZ * D_SZ + 255) / 256, 256>>>(Wtheta, Wphi);
    k_feat<<<B_SZ / 128, 256, SMEM_BYTES>>>(x_im, btheta);        // x_feat
    k_score2<<<B_SZ * K_SZ / 128, 256>>>(p_im, bphi);             // cheap + cands
    k_refine3<<<LISTMAX / 64, 128>>>(p_im, bphi);                 // exact refine
    k_output<<<B_SZ, 256>>>(x, p, Wg, bg, Wo, bo, sig_scale, sig_shift, out);
}

// round 13
// speedup vs baseline: 1.6678x; 1.4895x over previous
#include <cuda_runtime.h>
#include <cuda_bf16.h>
#include <cstdint>

#define B_SZ 2048
#define K_SZ 64
#define D_SZ 768      // C*E*E
#define F_SZ 64       // CF_FEAT
#define KC   64       // k elements per chunk
#define NCHUNK (D_SZ / KC)   // 12
#define CAP  16       // max candidates per b
#define DELTA 0.006f  // candidate margin
#define LISTMAX (B_SZ * CAP)

// ---------------- device scratch ----------------
__device__ float g_Xf[B_SZ * F_SZ];
__device__ int   g_cand[B_SZ * CAP];
__device__ int   g_ccnt[B_SZ];
__device__ float g_rs[B_SZ * CAP];
__device__ int   g_ncand;
__device__ int   g_list_gi[LISTMAX];
__device__ int   g_list_row[LISTMAX];
__device__ __align__(16) __nv_bfloat16 g_BphHi[F_SZ * D_SZ];
__device__ __align__(16) __nv_bfloat16 g_BphLo[F_SZ * D_SZ];
__device__ __align__(16) __nv_bfloat16 g_BthHi[F_SZ * D_SZ];
__device__ __align__(16) __nv_bfloat16 g_BthLo[F_SZ * D_SZ];

// ---------------- helpers ----------------
__device__ __forceinline__ uint32_t smem_u32(const void* p) {
    uint32_t a;
    asm("{ .reg .u64 t; cvta.to.shared.u64 t, %1; cvt.u32.u64 %0, t; }"
        : "=r"(a) : "l"(p));
    return a;
}
#define LDSM4(r, addr) \
    asm volatile("ldmatrix.sync.aligned.m8n8.x4.shared.b16 {%0,%1,%2,%3}, [%4];" \
        : "=r"((r)[0]), "=r"((r)[1]), "=r"((r)[2]), "=r"((r)[3]) : "r"(addr))
#define MMA16816(c, a, b0, b1) \
    asm volatile("mma.sync.aligned.m16n8k16.row.col.f32.bf16.bf16.f32 " \
        "{%0,%1,%2,%3}, {%4,%5,%6,%7}, {%8,%9}, {%0,%1,%2,%3};" \
        : "+f"((c)[0]), "+f"((c)[1]), "+f"((c)[2]), "+f"((c)[3]) \
        : "r"((a)[0]), "r"((a)[1]), "r"((a)[2]), "r"((a)[3]), "r"(b0), "r"(b1))

__device__ __forceinline__ uint32_t pack_hi(float x, float y,
                                            float& lx, float& ly) {
    __nv_bfloat16 hx = __float2bfloat16(x), hy = __float2bfloat16(y);
    lx = x - __bfloat162float(hx);
    ly = y - __bfloat162float(hy);
    return ((uint32_t)__bfloat16_as_ushort(hy) << 16) | __bfloat16_as_ushort(hx);
}
__device__ __forceinline__ uint32_t pack_bf(float x, float y) {
    return ((uint32_t)__bfloat16_as_ushort(__float2bfloat16(y)) << 16)
         | __bfloat16_as_ushort(__float2bfloat16(x));
}

// ---------------- K0: split W's into bf16 hi/lo + reset counter ------------
__global__ void k_prep(const float* __restrict__ Wth, const float* __restrict__ Wph) {
    int i = blockIdx.x * 256 + threadIdx.x;
    if (i == 0) g_ncand = 0;
    if (i < F_SZ * D_SZ) {
        float a = Wph[i];
        __nv_bfloat16 h = __float2bfloat16(a);
        g_BphHi[i] = h;
        g_BphLo[i] = __float2bfloat16(a - __bfloat162float(h));
        float b = Wth[i];
        __nv_bfloat16 g = __float2bfloat16(b);
        g_BthHi[i] = g;
        g_BthLo[i] = __float2bfloat16(b - __bfloat162float(g));
    }
}

// ================= x_feat kernel (3-pass, 16 CTAs, 128 rows) ==============
#define OFF_AHI   0
#define OFF_ALO   18432
#define OFF_BHI   36864
#define OFF_BLO   46080
#define OFF_BIAS  55296
#define SMEM_BYTES 55552

__global__ __launch_bounds__(256) void k_feat(const float* __restrict__ src,
                                              const float* __restrict__ bias) {
    extern __shared__ __align__(16) char sp[];
    const uint32_t sb = smem_u32(sp);
    const int tid = threadIdx.x;
    const int w = tid >> 5, lane = tid & 31;

    if (tid < F_SZ) ((float*)(sp + OFF_BIAS))[tid] = bias[tid];

    const float* Ab = src + (size_t)blockIdx.x * 128 * D_SZ;

    float4 ar[8];
    uint2 bh[4], bl[4];
#define LOAD_A(t) do {                                                          \
    _Pragma("unroll")                                                           \
    for (int i = 0; i < 8; i++) {                                               \
        int l = tid + 256 * i; int row = l >> 4, c4 = l & 15;                   \
        ar[i] = *(const float4*)(Ab + row * D_SZ + (t) * KC + c4 * 4);          \
    } } while (0)
#define LOAD_B(t) do {                                                          \
    _Pragma("unroll")                                                           \
    for (int i = 0; i < 4; i++) {                                               \
        int l = tid + 256 * i; int row = l >> 4, u = l & 15;                    \
        bh[i] = *(const uint2*)(g_BthHi + row * D_SZ + (t) * KC + u * 4);       \
        bl[i] = *(const uint2*)(g_BthLo + row * D_SZ + (t) * KC + u * 4);       \
    } } while (0)

    LOAD_A(0); LOAD_B(0);

    float acc[8][4];
#pragma unroll
    for (int j = 0; j < 8; j++)
#pragma unroll
        for (int q = 0; q < 4; q++) acc[j][q] = 0.f;

    const int m8  = lane & 7;
    const int grp = lane >> 3;
    const uint32_t aoffBase = (uint32_t)((16 * w + (grp & 1) * 8 + m8) * 144
                                         + ((grp >> 1) * 8) * 2);
    const uint32_t brow     = (uint32_t)(((grp >> 1) * 8 + m8) * 144);
    const uint32_t bcolg    = (uint32_t)(((grp & 1) * 8) * 2);

#pragma unroll 1
    for (int t = 0; t < NCHUNK; t++) {
#pragma unroll
        for (int i = 0; i < 8; i++) {
            int l = tid + 256 * i; int row = l >> 4, c4 = l & 15;
            float4 v = ar[i];
            float l0, l1, l2, l3;
            uint32_t h01 = pack_hi(v.x, v.y, l0, l1);
            uint32_t h23 = pack_hi(v.z, v.w, l2, l3);
            uint32_t q01 = pack_bf(l0, l1);
            uint32_t q23 = pack_bf(l2, l3);
            uint32_t off = (uint32_t)(row * 144 + c4 * 8);
            *(uint2*)(sp + OFF_AHI + off) = make_uint2(h01, h23);
            *(uint2*)(sp + OFF_ALO + off) = make_uint2(q01, q23);
        }
#pragma unroll
        for (int i = 0; i < 4; i++) {
            int l = tid + 256 * i; int row = l >> 4, u = l & 15;
            uint32_t off = (uint32_t)(row * 144 + u * 8);
            *(uint2*)(sp + OFF_BHI + off) = bh[i];
            *(uint2*)(sp + OFF_BLO + off) = bl[i];
        }
        __syncthreads();

        if (t + 1 < NCHUNK) { LOAD_A(t + 1); LOAD_B(t + 1); }

#pragma unroll
        for (int ks = 0; ks < 4; ks++) {
            uint32_t ah[4], al[4];
            uint32_t aoff = aoffBase + (uint32_t)(ks * 32);
            LDSM4(ah, sb + OFF_AHI + aoff);
            LDSM4(al, sb + OFF_ALO + aoff);
#pragma unroll
            for (int tp = 0; tp < 4; tp++) {
                uint32_t bhr[4], blr[4];
                uint32_t boff = (uint32_t)(tp * 16 * 144) + brow
                              + bcolg + (uint32_t)(ks * 32);
                LDSM4(bhr, sb + OFF_BHI + boff);
                LDSM4(blr, sb + OFF_BLO + boff);
                MMA16816(acc[2 * tp],     ah, bhr[0], bhr[1]);
                MMA16816(acc[2 * tp + 1], ah, bhr[2], bhr[3]);
                MMA16816(acc[2 * tp],     ah, blr[0], blr[1]);
                MMA16816(acc[2 * tp + 1], ah, blr[2], blr[3]);
                MMA16816(acc[2 * tp],     al, bhr[0], bhr[1]);
                MMA16816(acc[2 * tp + 1], al, bhr[2], bhr[3]);
            }
        }
        __syncthreads();
    }

    const int qr = lane >> 2, qc = lane & 3;
    const float* bs = (const float*)(sp + OFF_BIAS);
#pragma unroll
    for (int h = 0; h < 2; h++) {
        const int row = 16 * w + h * 8 + qr;
        float n2 = 0.f;
#pragma unroll
        for (int j = 0; j < 8; j++) {
            int c = j * 8 + qc * 2;
            float v0 = acc[j][h * 2 + 0] + bs[c];
            float v1 = acc[j][h * 2 + 1] + bs[c + 1];
            n2 = fmaf(v0, v0, n2); n2 = fmaf(v1, v1, n2);
        }
        n2 += __shfl_xor_sync(0xffffffffu, n2, 1);
        n2 += __shfl_xor_sync(0xffffffffu, n2, 2);
        float inv = 1.0f / fmaxf(sqrtf(n2), 1e-12f);
        float* o = g_Xf + ((size_t)blockIdx.x * 128 + row) * 64;
#pragma unroll
        for (int j = 0; j < 8; j++) {
            int c = j * 8 + qc * 2;
            o[c]     = (acc[j][h * 2 + 0] + bs[c]) * inv;
            o[c + 1] = (acc[j][h * 2 + 1] + bs[c + 1]) * inv;
        }
    }
}

// ================= Stage 1: 64 rows/CTA (one b), warp tile 16x32 ===========
__global__ __launch_bounds__(256) void k_score3(
    const float* __restrict__ p_im, const float* __restrict__ bphi)
{
    __shared__ __align__(16) char sA[64 * 144];
    __shared__ __align__(16) char sB[64 * 144];
    __shared__ float sXf[64];
    __shared__ float sBias[64];
    __shared__ float sPart[64][4];
    __shared__ float sSc[64];

    const uint32_t sbA = smem_u32(sA), sbB = smem_u32(sB);
    const int tid = threadIdx.x;
    const int w = tid >> 5, lane = tid & 31;
    const int rg = w >> 1, cg = w & 1;
    const int b = blockIdx.x;

    if (tid < 64) {
        sBias[tid] = bphi[tid];
        sXf[tid] = g_Xf[(size_t)b * 64 + tid];
    }

    const float* Ab = p_im + (size_t)b * K_SZ * D_SZ;

    float4 ar[4];
    uint2 bh[4];
#define S3_LOAD_A(t) do {                                                       \
    _Pragma("unroll")                                                           \
    for (int i = 0; i < 4; i++) {                                               \
        int l = tid + 256 * i; int row = l >> 4, c4 = l & 15;                   \
        ar[i] = *(const float4*)(Ab + row * D_SZ + (t) * KC + c4 * 4);          \
    } } while (0)
#define S3_LOAD_B(t) do {                                                       \
    _Pragma("unroll")                                                           \
    for (int i = 0; i < 4; i++) {                                               \
        int l = tid + 256 * i; int row = l >> 4, u = l & 15;                    \
        bh[i] = *(const uint2*)(g_BphHi + row * D_SZ + (t) * KC + u * 4);       \
    } } while (0)

    S3_LOAD_A(0); S3_LOAD_B(0);

    float acc[4][4];
#pragma unroll
    for (int j = 0; j < 4; j++)
#pragma unroll
        for (int q = 0; q < 4; q++) acc[j][q] = 0.f;

    const int m8  = lane & 7;
    const int grp = lane >> 3;
    const uint32_t aoffBase = (uint32_t)((rg * 16 + (grp & 1) * 8 + m8) * 144
                                         + ((grp >> 1) * 8) * 2);
    const uint32_t bbase = (uint32_t)((cg * 32 + (grp >> 1) * 8 + m8) * 144
                                      + (grp & 1) * 16);

#pragma unroll 1
    for (int t = 0; t < NCHUNK; t++) {
#pragma unroll
        for (int i = 0; i < 4; i++) {
            int l = tid + 256 * i; int row = l >> 4, c4 = l & 15;
            float4 v = ar[i];
            uint32_t h01 = pack_bf(v.x, v.y);
            uint32_t h23 = pack_bf(v.z, v.w);
            *(uint2*)(sA + (uint32_t)(row * 144 + c4 * 8)) = make_uint2(h01, h23);
        }
#pragma unroll
        for (int i = 0; i < 4; i++) {
            int l = tid + 256 * i; int row = l >> 4, u = l & 15;
            *(uint2*)(sB + (uint32_t)(row * 144 + u * 8)) = bh[i];
        }
        __syncthreads();

        if (t + 1 < NCHUNK) { S3_LOAD_A(t + 1); S3_LOAD_B(t + 1); }

#pragma unroll
        for (int ks = 0; ks < 4; ks++) {
            uint32_t ah[4];
            LDSM4(ah, sbA + aoffBase + (uint32_t)(ks * 32));
#pragma unroll
            for (int tp = 0; tp < 2; tp++) {
                uint32_t bhr[4];
                LDSM4(bhr, sbB + bbase + (uint32_t)(tp * 16 * 144 + ks * 32));
                MMA16816(acc[2 * tp],     ah, bhr[0], bhr[1]);
                MMA16816(acc[2 * tp + 1], ah, bhr[2], bhr[3]);
            }
        }
        __syncthreads();
    }

    // ---- epilogue: bias + partial norm/dot, cross-warp combine ----
    const int qr = lane >> 2, qc = lane & 3;
#pragma unroll
    for (int h = 0; h < 2; h++) {
        const int row = rg * 16 + h * 8 + qr;
        float n2 = 0.f, dp = 0.f;
#pragma unroll
        for (int j = 0; j < 4; j++) {
            int c = cg * 32 + j * 8 + qc * 2;
            float v0 = acc[j][h * 2 + 0] + sBias[c];
            float v1 = acc[j][h * 2 + 1] + sBias[c + 1];
            n2 = fmaf(v0, v0, n2); n2 = fmaf(v1, v1, n2);
            dp = fmaf(sXf[c], v0, dp); dp = fmaf(sXf[c + 1], v1, dp);
        }
        n2 += __shfl_xor_sync(0xffffffffu, n2, 1);
        n2 += __shfl_xor_sync(0xffffffffu, n2, 2);
        dp += __shfl_xor_sync(0xffffffffu, dp, 1);
        dp += __shfl_xor_sync(0xffffffffu, dp, 2);
        if (qc == 0) { sPart[row][cg * 2] = n2; sPart[row][cg * 2 + 1] = dp; }
    }
    __syncthreads();
    if (tid < 64) {
        float n2 = sPart[tid][0] + sPart[tid][2];
        float dp = sPart[tid][1] + sPart[tid][3];
        sSc[tid] = dp / fmaxf(sqrtf(n2), 1e-12f);
    }
    __syncthreads();

    // ---- candidate selection + push (warp 0) ----
    if (w == 0) {
        float s0 = sSc[lane];
        float s1 = sSc[32 + lane];
        float m = fmaxf(s0, s1);
#pragma unroll
        for (int o = 16; o; o >>= 1)
            m = fmaxf(m, __shfl_xor_sync(0xffffffffu, m, o));
        float thr = m - DELTA;
        unsigned b0m = __ballot_sync(0xffffffffu, s0 > thr);
        unsigned b1m = __ballot_sync(0xffffffffu, s1 > thr);
        int c0 = __popc(b0m);
        int cnt = min(c0 + __popc(b1m), CAP);
        unsigned lt = (1u << lane) - 1u;
        int gbase = 0;
        if (lane == 0) {
            g_ccnt[b] = cnt;
            gbase = atomicAdd(&g_ncand, cnt);
        }
        gbase = __shfl_sync(0xffffffffu, gbase, 0);
        if (s0 > thr) {
            int slot = __popc(b0m & lt);
            if (slot < CAP) {
                g_cand[b * CAP + slot] = lane;
                g_list_gi[gbase + slot] = b * CAP + slot;
                g_list_row[gbase + slot] = b * K_SZ + lane;
            }
        }
        if (s1 > thr) {
            int slot = c0 + __popc(b1m & lt);
            if (slot < CAP) {
                g_cand[b * CAP + slot] = 32 + lane;
                g_list_gi[gbase + slot] = b * CAP + slot;
                g_list_row[gbase + slot] = b * K_SZ + 32 + lane;
            }
        }
    }
}

// ================= Stage 2: 3-pass refine, 32 rows/CTA, 128 thr ============
__global__ __launch_bounds__(128) void k_refine4(
    const float* __restrict__ p_im, const float* __restrict__ bphi)
{
    __shared__ __align__(16) char sAhi[32 * 144];
    __shared__ __align__(16) char sAlo[32 * 144];
    __shared__ __align__(16) char sBhi[64 * 144];
    __shared__ __align__(16) char sBlo[64 * 144];
    __shared__ float sBias[64];
    __shared__ int   sGI[32];
    __shared__ int   sBI[32];
    __shared__ const float* sPtr[32];
    __shared__ float sPart[32][4];

    const uint32_t sbAh = smem_u32(sAhi), sbAl = smem_u32(sAlo);
    const uint32_t sbBh = smem_u32(sBhi), sbBl = smem_u32(sBlo);
    const int tid = threadIdx.x;
    const int w = tid >> 5, lane = tid & 31;
    const int rg = w >> 1, cg = w & 1;
    const int N = g_ncand;
    const int base = blockIdx.x * 32;
    if (base >= N) return;

    if (tid < 64) sBias[tid] = bphi[tid];
    if (tid < 32) {
        int e = min(base + tid, N - 1);
        int rowid = g_list_row[e];
        sGI[tid] = g_list_gi[e];
        sBI[tid] = rowid >> 6;
        sPtr[tid] = p_im + (size_t)rowid * D_SZ;
    }
    __syncthreads();

    float4 ar[4];
    uint2 bh[8], bl[8];
#define R4_LOAD_A(t) do {                                                       \
    _Pragma("unroll")                                                           \
    for (int i = 0; i < 4; i++) {                                               \
        int l = tid + 128 * i; int row = l >> 4, c4 = l & 15;                   \
        ar[i] = *(const float4*)(sPtr[row] + (t) * KC + c4 * 4);                \
    } } while (0)
#define R4_LOAD_B(t) do {                                                       \
    _Pragma("unroll")                                                           \
    for (int i = 0; i < 8; i++) {                                               \
        int l = tid + 128 * i; int row = l >> 4, u = l & 15;                    \
        bh[i] = *(const uint2*)(g_BphHi + row * D_SZ + (t) * KC + u * 4);       \
        bl[i] = *(const uint2*)(g_BphLo + row * D_SZ + (t) * KC + u * 4);       \
    } } while (0)

    R4_LOAD_A(0); R4_LOAD_B(0);

    float acc[4][4];
#pragma unroll
    for (int j = 0; j < 4; j++)
#pragma unroll
        for (int q = 0; q < 4; q++) acc[j][q] = 0.f;

    const int m8  = lane & 7;
    const int grp = lane >> 3;
    const uint32_t aoffBase = (uint32_t)((rg * 16 + (grp & 1) * 8 + m8) * 144
                                         + ((grp >> 1) * 8) * 2);
    const uint32_t bbase = (uint32_t)((cg * 32 + (grp >> 1) * 8 + m8) * 144
                                      + (grp & 1) * 16);

#pragma unroll 1
    for (int t = 0; t < NCHUNK; t++) {
#pragma unroll
        for (int i = 0; i < 4; i++) {
            int l = tid + 128 * i; int row = l >> 4, c4 = l & 15;
            float4 v = ar[i];
            float l0, l1, l2, l3;
            uint32_t h01 = pack_hi(v.x, v.y, l0, l1);
            uint32_t h23 = pack_hi(v.z, v.w, l2, l3);
            uint32_t q01 = pack_bf(l0, l1);
            uint32_t q23 = pack_bf(l2, l3);
            uint32_t off = (uint32_t)(row * 144 + c4 * 8);
            *(uint2*)(sAhi + off) = make_uint2(h01, h23);
            *(uint2*)(sAlo + off) = make_uint2(q01, q23);
        }
#pragma unroll
        for (int i = 0; i < 8; i++) {
            int l = tid + 128 * i; int row = l >> 4, u = l & 15;
            uint32_t off = (uint32_t)(row * 144 + u * 8);
            *(uint2*)(sBhi + off) = bh[i];
            *(uint2*)(sBlo + off) = bl[i];
        }
        __syncthreads();

        if (t + 1 < NCHUNK) { R4_LOAD_A(t + 1); R4_LOAD_B(t + 1); }

#pragma unroll
        for (int ks = 0; ks < 4; ks++) {
            uint32_t ah[4], al[4];
            uint32_t aoff = aoffBase + (uint32_t)(ks * 32);
            LDSM4(ah, sbAh + aoff);
            LDSM4(al, sbAl + aoff);
#pragma unroll
            for (int tp = 0; tp < 2; tp++) {
                uint32_t bhr[4], blr[4];
                uint32_t boff = bbase + (uint32_t)(tp * 16 * 144 + ks * 32);
                LDSM4(bhr, sbBh + boff);
                LDSM4(blr, sbBl + boff);
                MMA16816(acc[2 * tp],     ah, bhr[0], bhr[1]);
                MMA16816(acc[2 * tp + 1], ah, bhr[2], bhr[3]);
                MMA16816(acc[2 * tp],     ah, blr[0], blr[1]);
                MMA16816(acc[2 * tp + 1], ah, blr[2], blr[3]);
                MMA16816(acc[2 * tp],     al, bhr[0], bhr[1]);
                MMA16816(acc[2 * tp + 1], al, bhr[2], bhr[3]);
            }
        }
        __syncthreads();
    }

    const int qr = lane >> 2, qc = lane & 3;
#pragma unroll
    for (int h = 0; h < 2; h++) {
        const int row = rg * 16 + h * 8 + qr;
        const float* xf = g_Xf + (size_t)sBI[row] * 64;
        float n2 = 0.f, dp = 0.f;
#pragma unroll
        for (int j = 0; j < 4; j++) {
            int c = cg * 32 + j * 8 + qc * 2;
            float v0 = acc[j][h * 2 + 0] + sBias[c];
            float v1 = acc[j][h * 2 + 1] + sBias[c + 1];
            n2 = fmaf(v0, v0, n2); n2 = fmaf(v1, v1, n2);
            dp = fmaf(xf[c], v0, dp); dp = fmaf(xf[c + 1], v1, dp);
        }
        n2 += __shfl_xor_sync(0xffffffffu, n2, 1);
        n2 += __shfl_xor_sync(0xffffffffu, n2, 2);
        dp += __shfl_xor_sync(0xffffffffu, dp, 1);
        dp += __shfl_xor_sync(0xffffffffu, dp, 2);
        if (qc == 0) { sPart[row][cg * 2] = n2; sPart[row][cg * 2 + 1] = dp; }
    }
    __syncthreads();
    if (tid < 32 && base + tid < N) {
        float n2 = sPart[tid][0] + sPart[tid][2];
        float dp = sPart[tid][1] + sPart[tid][3];
        g_rs[sGI[tid]] = dp / fmaxf(sqrtf(n2), 1e-12f);
    }
}

// ================= K3: switch + candidate softmax + sparse sum + mix =======
__global__ __launch_bounds__(256) void k_output(
    const float* __restrict__ x, const float* __restrict__ p,
    const float* __restrict__ Wg, const float* __restrict__ bg,
    const float* __restrict__ Wo, const float* __restrict__ bo,
    const float* __restrict__ sig_scale, const float* __restrict__ sig_shift,
    float* __restrict__ out)
{
    __shared__ float wsm[CAP];
    __shared__ int   kk[CAP];
    __shared__ int   s_cnt;
    __shared__ float s_sw;
    const int b = blockIdx.x, tid = threadIdx.x;

    // hoist x loads to overlap latency under the softmax prep
    const float* xb = x + (size_t)b * D_SZ;
    float xv0 = xb[tid], xv1 = xb[tid + 256], xv2 = xb[tid + 512];

    if (tid < 32) {
        const int cnt = g_ccnt[b];
        float s = (tid < cnt) ? g_rs[b * CAP + tid] : -1e30f;
        float m = s;
#pragma unroll
        for (int o = 16; o; o >>= 1)
            m = fmaxf(m, __shfl_xor_sync(0xffffffffu, m, o));
        float e = (tid < cnt) ? expf(1048576.0f * (s - m)) : 0.f;
        float sum = e;
#pragma unroll
        for (int o = 16; o; o >>= 1)
            sum += __shfl_xor_sync(0xffffffffu, sum, o);
        if (tid < cnt) {
            wsm[tid] = e / sum;
            kk[tid]  = g_cand[b * CAP + tid];
        }
        if (tid == 0) {
            s_cnt = cnt;
            float z = m * sig_scale[0] + sig_shift[0];
            s_sw = 1.0f / (1.0f + expf(-z));
        }
    }
    __syncthreads();

    const int cnt = s_cnt;
    const float sw = s_sw;
    float acc0 = 0.f, acc1 = 0.f, acc2 = 0.f;
    const float* pb = p + (size_t)b * K_SZ * D_SZ;
    for (int i = 0; i < cnt; i++) {
        float wk = wsm[i];
        if (wk > 1e-12f) {
            const float* pr = pb + kk[i] * D_SZ;
            acc0 = fmaf(wk, pr[tid],       acc0);
            acc1 = fmaf(wk, pr[tid + 256], acc1);
            acc2 = fmaf(wk, pr[tid + 512], acc2);
        }
    }

    float mx0 = fmaf(Wg[0], acc0, fmaf(Wg[1], acc1, fmaf(Wg[2], acc2, bg[0])));
    float mx1 = fmaf(Wg[3], acc0, fmaf(Wg[4], acc1, fmaf(Wg[5], acc2, bg[1])));
    float mx2 = fmaf(Wg[6], acc0, fmaf(Wg[7], acc1, fmaf(Wg[8], acc2, bg[2])));

    float* ob = out + (size_t)b * D_SZ;
    float pa0 = fmaf(Wo[0], mx0, fmaf(Wo[1], mx1, fmaf(Wo[2], mx2, bo[0])));
    float pa1 = fmaf(Wo[3], mx0, fmaf(Wo[4], mx1, fmaf(Wo[5], mx2, bo[1])));
    float pa2 = fmaf(Wo[6], mx0, fmaf(Wo[7], mx1, fmaf(Wo[8], mx2, bo[2])));
    ob[tid]       = xv0 * (1.0f - sw) + pa0 * sw;
    ob[tid + 256] = xv1 * (1.0f - sw) + pa1 * sw;
    ob[tid + 512] = xv2 * (1.0f - sw) + pa2 * sw;
}

// ---------------- launch ----------------
extern "C" void kernel_launch(void* const* d_in, const int* in_sizes, int n_in,
                              void* d_out, int out_size) {
    const float* x         = (const float*)d_in[0];
    const float* p         = (const float*)d_in[1];
    const float* x_im      = (const float*)d_in[2];
    const float* p_im      = (const float*)d_in[3];
    const float* Wtheta    = (const float*)d_in[4];
    const float* btheta    = (const float*)d_in[5];
    const float* Wphi      = (const float*)d_in[6];
    const float* bphi      = (const float*)d_in[7];
    const float* Wg        = (const float*)d_in[8];
    const float* bg        = (const float*)d_in[9];
    const float* Wo        = (const float*)d_in[10];
    const float* bo        = (const float*)d_in[11];
    const float* sig_scale = (const float*)d_in[12];
    const float* sig_shift = (const float*)d_in[13];
    float* out = (float*)d_out;

    static int s_attr_done = 0;
    if (!s_attr_done) {
        cudaFuncSetAttribute(k_feat, cudaFuncAttributeMaxDynamicSharedMemorySize,
                             SMEM_BYTES);
        s_attr_done = 1;
    }

    k_prep<<<(F_SZ * D_SZ + 255) / 256, 256>>>(Wtheta, Wphi);
    k_feat<<<B_SZ / 128, 256, SMEM_BYTES>>>(x_im, btheta);        // x_feat
    k_score3<<<B_SZ, 256>>>(p_im, bphi);                          // cheap + cands
    k_refine4<<<LISTMAX / 32, 128>>>(p_im, bphi);                 // exact refine
    k_output<<<B_SZ, 256>>>(x, p, Wg, bg, Wo, bo, sig_scale, sig_shift, out);
}

// round 14
// speedup vs baseline: 1.6726x; 1.0029x over previous
#include <cuda_runtime.h>
#include <cuda_bf16.h>
#include <cstdint>

#define B_SZ 2048
#define K_SZ 64
#define D_SZ 768      // C*E*E
#define F_SZ 64       // CF_FEAT
#define KC   64       // k elements per chunk
#define NCHUNK (D_SZ / KC)   // 12
#define CAP  16       // max candidates per b
#define DELTA 0.006f  // candidate margin
#define LISTMAX (B_SZ * CAP)

// ---------------- device scratch ----------------
__device__ float g_Xf[B_SZ * F_SZ];
__device__ int   g_cand[B_SZ * CAP];
__device__ int   g_ccnt[B_SZ];
__device__ float g_rs[B_SZ * CAP];
__device__ int   g_ncand;
__device__ int   g_list_gi[LISTMAX];
__device__ int   g_list_row[LISTMAX];
__device__ __align__(16) __nv_bfloat16 g_BphHi[F_SZ * D_SZ];
__device__ __align__(16) __nv_bfloat16 g_BphLo[F_SZ * D_SZ];
__device__ __align__(16) __nv_bfloat16 g_BthHi[F_SZ * D_SZ];
__device__ __align__(16) __nv_bfloat16 g_BthLo[F_SZ * D_SZ];

// ---------------- helpers ----------------
__device__ __forceinline__ uint32_t smem_u32(const void* p) {
    uint32_t a;
    asm("{ .reg .u64 t; cvta.to.shared.u64 t, %1; cvt.u32.u64 %0, t; }"
        : "=r"(a) : "l"(p));
    return a;
}
#define LDSM4(r, addr) \
    asm volatile("ldmatrix.sync.aligned.m8n8.x4.shared.b16 {%0,%1,%2,%3}, [%4];" \
        : "=r"((r)[0]), "=r"((r)[1]), "=r"((r)[2]), "=r"((r)[3]) : "r"(addr))
#define MMA16816(c, a, b0, b1) \
    asm volatile("mma.sync.aligned.m16n8k16.row.col.f32.bf16.bf16.f32 " \
        "{%0,%1,%2,%3}, {%4,%5,%6,%7}, {%8,%9}, {%0,%1,%2,%3};" \
        : "+f"((c)[0]), "+f"((c)[1]), "+f"((c)[2]), "+f"((c)[3]) \
        : "r"((a)[0]), "r"((a)[1]), "r"((a)[2]), "r"((a)[3]), "r"(b0), "r"(b1))

__device__ __forceinline__ uint32_t pack_hi(float x, float y,
                                            float& lx, float& ly) {
    __nv_bfloat16 hx = __float2bfloat16(x), hy = __float2bfloat16(y);
    lx = x - __bfloat162float(hx);
    ly = y - __bfloat162float(hy);
    return ((uint32_t)__bfloat16_as_ushort(hy) << 16) | __bfloat16_as_ushort(hx);
}
__device__ __forceinline__ uint32_t pack_bf(float x, float y) {
    return ((uint32_t)__bfloat16_as_ushort(__float2bfloat16(y)) << 16)
         | __bfloat16_as_ushort(__float2bfloat16(x));
}

// ---------------- K0: split W's into bf16 hi/lo + reset counter ------------
__global__ void k_prep(const float* __restrict__ Wth, const float* __restrict__ Wph) {
    int i = blockIdx.x * 256 + threadIdx.x;
    if (i == 0) g_ncand = 0;
    if (i < F_SZ * D_SZ) {
        float a = Wph[i];
        __nv_bfloat16 h = __float2bfloat16(a);
        g_BphHi[i] = h;
        g_BphLo[i] = __float2bfloat16(a - __bfloat162float(h));
        float b = Wth[i];
        __nv_bfloat16 g = __float2bfloat16(b);
        g_BthHi[i] = g;
        g_BthLo[i] = __float2bfloat16(b - __bfloat162float(g));
    }
}

// ================= x_feat kernel (3-pass, 16 CTAs, 128 rows) ==============
#define OFF_AHI   0
#define OFF_ALO   18432
#define OFF_BHI   36864
#define OFF_BLO   46080
#define OFF_BIAS  55296
#define SMEM_BYTES 55552

__global__ __launch_bounds__(256) void k_feat(const float* __restrict__ src,
                                              const float* __restrict__ bias) {
    extern __shared__ __align__(16) char sp[];
    const uint32_t sb = smem_u32(sp);
    const int tid = threadIdx.x;
    const int w = tid >> 5, lane = tid & 31;

    if (tid < F_SZ) ((float*)(sp + OFF_BIAS))[tid] = bias[tid];

    const float* Ab = src + (size_t)blockIdx.x * 128 * D_SZ;

    float4 ar[8];
    uint2 bh[4], bl[4];
#define LOAD_A(t) do {                                                          \
    _Pragma("unroll")                                                           \
    for (int i = 0; i < 8; i++) {                                               \
        int l = tid + 256 * i; int row = l >> 4, c4 = l & 15;                   \
        ar[i] = *(const float4*)(Ab + row * D_SZ + (t) * KC + c4 * 4);          \
    } } while (0)
#define LOAD_B(t) do {                                                          \
    _Pragma("unroll")                                                           \
    for (int i = 0; i < 4; i++) {                                               \
        int l = tid + 256 * i; int row = l >> 4, u = l & 15;                    \
        bh[i] = *(const uint2*)(g_BthHi + row * D_SZ + (t) * KC + u * 4);       \
        bl[i] = *(const uint2*)(g_BthLo + row * D_SZ + (t) * KC + u * 4);       \
    } } while (0)

    LOAD_A(0); LOAD_B(0);

    float acc[8][4];
#pragma unroll
    for (int j = 0; j < 8; j++)
#pragma unroll
        for (int q = 0; q < 4; q++) acc[j][q] = 0.f;

    const int m8  = lane & 7;
    const int grp = lane >> 3;
    const uint32_t aoffBase = (uint32_t)((16 * w + (grp & 1) * 8 + m8) * 144
                                         + ((grp >> 1) * 8) * 2);
    const uint32_t brow     = (uint32_t)(((grp >> 1) * 8 + m8) * 144);
    const uint32_t bcolg    = (uint32_t)(((grp & 1) * 8) * 2);

#pragma unroll 1
    for (int t = 0; t < NCHUNK; t++) {
#pragma unroll
        for (int i = 0; i < 8; i++) {
            int l = tid + 256 * i; int row = l >> 4, c4 = l & 15;
            float4 v = ar[i];
            float l0, l1, l2, l3;
            uint32_t h01 = pack_hi(v.x, v.y, l0, l1);
            uint32_t h23 = pack_hi(v.z, v.w, l2, l3);
            uint32_t q01 = pack_bf(l0, l1);
            uint32_t q23 = pack_bf(l2, l3);
            uint32_t off = (uint32_t)(row * 144 + c4 * 8);
            *(uint2*)(sp + OFF_AHI + off) = make_uint2(h01, h23);
            *(uint2*)(sp + OFF_ALO + off) = make_uint2(q01, q23);
        }
#pragma unroll
        for (int i = 0; i < 4; i++) {
            int l = tid + 256 * i; int row = l >> 4, u = l & 15;
            uint32_t off = (uint32_t)(row * 144 + u * 8);
            *(uint2*)(sp + OFF_BHI + off) = bh[i];
            *(uint2*)(sp + OFF_BLO + off) = bl[i];
        }
        __syncthreads();

        if (t + 1 < NCHUNK) { LOAD_A(t + 1); LOAD_B(t + 1); }

#pragma unroll
        for (int ks = 0; ks < 4; ks++) {
            uint32_t ah[4], al[4];
            uint32_t aoff = aoffBase + (uint32_t)(ks * 32);
            LDSM4(ah, sb + OFF_AHI + aoff);
            LDSM4(al, sb + OFF_ALO + aoff);
#pragma unroll
            for (int tp = 0; tp < 4; tp++) {
                uint32_t bhr[4], blr[4];
                uint32_t boff = (uint32_t)(tp * 16 * 144) + brow
                              + bcolg + (uint32_t)(ks * 32);
                LDSM4(bhr, sb + OFF_BHI + boff);
                LDSM4(blr, sb + OFF_BLO + boff);
                MMA16816(acc[2 * tp],     ah, bhr[0], bhr[1]);
                MMA16816(acc[2 * tp + 1], ah, bhr[2], bhr[3]);
                MMA16816(acc[2 * tp],     ah, blr[0], blr[1]);
                MMA16816(acc[2 * tp + 1], ah, blr[2], blr[3]);
                MMA16816(acc[2 * tp],     al, bhr[0], bhr[1]);
                MMA16816(acc[2 * tp + 1], al, bhr[2], bhr[3]);
            }
        }
        __syncthreads();
    }

    const int qr = lane >> 2, qc = lane & 3;
    const float* bs = (const float*)(sp + OFF_BIAS);
#pragma unroll
    for (int h = 0; h < 2; h++) {
        const int row = 16 * w + h * 8 + qr;
        float n2 = 0.f;
#pragma unroll
        for (int j = 0; j < 8; j++) {
            int c = j * 8 + qc * 2;
            float v0 = acc[j][h * 2 + 0] + bs[c];
            float v1 = acc[j][h * 2 + 1] + bs[c + 1];
            n2 = fmaf(v0, v0, n2); n2 = fmaf(v1, v1, n2);
        }
        n2 += __shfl_xor_sync(0xffffffffu, n2, 1);
        n2 += __shfl_xor_sync(0xffffffffu, n2, 2);
        float inv = 1.0f / fmaxf(sqrtf(n2), 1e-12f);
        float* o = g_Xf + ((size_t)blockIdx.x * 128 + row) * 64;
#pragma unroll
        for (int j = 0; j < 8; j++) {
            int c = j * 8 + qc * 2;
            o[c]     = (acc[j][h * 2 + 0] + bs[c]) * inv;
            o[c + 1] = (acc[j][h * 2 + 1] + bs[c + 1]) * inv;
        }
    }
}

// ================= Stage 1: 64 rows/CTA, double-buffered, 1 sync/chunk =====
__global__ __launch_bounds__(256) void k_score3(
    const float* __restrict__ p_im, const float* __restrict__ bphi)
{
    __shared__ __align__(16) char sA[2][64 * 144];
    __shared__ __align__(16) char sB[2][64 * 144];
    __shared__ float sXf[64];
    __shared__ float sBias[64];
    __shared__ float sPart[64][4];
    __shared__ float sSc[64];

    const uint32_t sbA = smem_u32(sA), sbB = smem_u32(sB);
    const int tid = threadIdx.x;
    const int w = tid >> 5, lane = tid & 31;
    const int rg = w >> 1, cg = w & 1;
    const int b = blockIdx.x;

    if (tid < 64) {
        sBias[tid] = bphi[tid];
        sXf[tid] = g_Xf[(size_t)b * 64 + tid];
    }

    const float* Ab = p_im + (size_t)b * K_SZ * D_SZ;

    float4 ar[4];
    uint2 bh[4];
#define S3_LOAD(t) do {                                                         \
    _Pragma("unroll")                                                           \
    for (int i = 0; i < 4; i++) {                                               \
        int l = tid + 256 * i; int row = l >> 4, c4 = l & 15;                   \
        ar[i] = *(const float4*)(Ab + row * D_SZ + (t) * KC + c4 * 4);          \
        bh[i] = *(const uint2*)(g_BphHi + row * D_SZ + (t) * KC + c4 * 4);      \
    } } while (0)
#define S3_STS(buf) do {                                                        \
    _Pragma("unroll")                                                           \
    for (int i = 0; i < 4; i++) {                                               \
        int l = tid + 256 * i; int row = l >> 4, c4 = l & 15;                   \
        float4 v = ar[i];                                                       \
        uint32_t h01 = pack_bf(v.x, v.y);                                       \
        uint32_t h23 = pack_bf(v.z, v.w);                                       \
        uint32_t off = (uint32_t)(row * 144 + c4 * 8);                          \
        *(uint2*)(sA[buf] + off) = make_uint2(h01, h23);                        \
        *(uint2*)(sB[buf] + off) = bh[i];                                       \
    } } while (0)

    S3_LOAD(0);
    S3_STS(0);
    __syncthreads();
    S3_LOAD(1);

    float acc[4][4];
#pragma unroll
    for (int j = 0; j < 4; j++)
#pragma unroll
        for (int q = 0; q < 4; q++) acc[j][q] = 0.f;

    const int m8  = lane & 7;
    const int grp = lane >> 3;
    const uint32_t aoffBase = (uint32_t)((rg * 16 + (grp & 1) * 8 + m8) * 144
                                         + ((grp >> 1) * 8) * 2);
    const uint32_t bbase = (uint32_t)((cg * 32 + (grp >> 1) * 8 + m8) * 144
                                      + (grp & 1) * 16);

#pragma unroll 1
    for (int t = 0; t < NCHUNK; t++) {
        const uint32_t abuf = sbA + (uint32_t)((t & 1) * 64 * 144);
        const uint32_t bbuf = sbB + (uint32_t)((t & 1) * 64 * 144);
#pragma unroll
        for (int ks = 0; ks < 4; ks++) {
            uint32_t ah[4];
            LDSM4(ah, abuf + aoffBase + (uint32_t)(ks * 32));
#pragma unroll
            for (int tp = 0; tp < 2; tp++) {
                uint32_t bhr[4];
                LDSM4(bhr, bbuf + bbase + (uint32_t)(tp * 16 * 144 + ks * 32));
                MMA16816(acc[2 * tp],     ah, bhr[0], bhr[1]);
                MMA16816(acc[2 * tp + 1], ah, bhr[2], bhr[3]);
            }
        }
        if (t + 1 < NCHUNK) {
            S3_STS((t + 1) & 1);
            if (t + 2 < NCHUNK) S3_LOAD(t + 2);
        }
        __syncthreads();
    }

    // ---- epilogue: bias + partial norm/dot, cross-warp combine ----
    const int qr = lane >> 2, qc = lane & 3;
#pragma unroll
    for (int h = 0; h < 2; h++) {
        const int row = rg * 16 + h * 8 + qr;
        float n2 = 0.f, dp = 0.f;
#pragma unroll
        for (int j = 0; j < 4; j++) {
            int c = cg * 32 + j * 8 + qc * 2;
            float v0 = acc[j][h * 2 + 0] + sBias[c];
            float v1 = acc[j][h * 2 + 1] + sBias[c + 1];
            n2 = fmaf(v0, v0, n2); n2 = fmaf(v1, v1, n2);
            dp = fmaf(sXf[c], v0, dp); dp = fmaf(sXf[c + 1], v1, dp);
        }
        n2 += __shfl_xor_sync(0xffffffffu, n2, 1);
        n2 += __shfl_xor_sync(0xffffffffu, n2, 2);
        dp += __shfl_xor_sync(0xffffffffu, dp, 1);
        dp += __shfl_xor_sync(0xffffffffu, dp, 2);
        if (qc == 0) { sPart[row][cg * 2] = n2; sPart[row][cg * 2 + 1] = dp; }
    }
    __syncthreads();
    if (tid < 64) {
        float n2 = sPart[tid][0] + sPart[tid][2];
        float dp = sPart[tid][1] + sPart[tid][3];
        sSc[tid] = dp / fmaxf(sqrtf(n2), 1e-12f);
    }
    __syncthreads();

    // ---- candidate selection + push (warp 0) ----
    if (w == 0) {
        float s0 = sSc[lane];
        float s1 = sSc[32 + lane];
        float m = fmaxf(s0, s1);
#pragma unroll
        for (int o = 16; o; o >>= 1)
            m = fmaxf(m, __shfl_xor_sync(0xffffffffu, m, o));
        float thr = m - DELTA;
        unsigned b0m = __ballot_sync(0xffffffffu, s0 > thr);
        unsigned b1m = __ballot_sync(0xffffffffu, s1 > thr);
        int c0 = __popc(b0m);
        int cnt = min(c0 + __popc(b1m), CAP);
        unsigned lt = (1u << lane) - 1u;
        int gbase = 0;
        if (lane == 0) {
            g_ccnt[b] = cnt;
            gbase = atomicAdd(&g_ncand, cnt);
        }
        gbase = __shfl_sync(0xffffffffu, gbase, 0);
        if (s0 > thr) {
            int slot = __popc(b0m & lt);
            if (slot < CAP) {
                g_cand[b * CAP + slot] = lane;
                g_list_gi[gbase + slot] = b * CAP + slot;
                g_list_row[gbase + slot] = b * K_SZ + lane;
            }
        }
        if (s1 > thr) {
            int slot = c0 + __popc(b1m & lt);
            if (slot < CAP) {
                g_cand[b * CAP + slot] = 32 + lane;
                g_list_gi[gbase + slot] = b * CAP + slot;
                g_list_row[gbase + slot] = b * K_SZ + 32 + lane;
            }
        }
    }
}

// ================= Stage 2: 3-pass refine, double-buffered =================
#define R4_AHI   0            // 2 x 4608
#define R4_ALO   9216         // 2 x 4608
#define R4_BHI   18432        // 2 x 9216
#define R4_BLO   36864        // 2 x 9216
#define R4_BIAS  55296
#define R4_GI    55552
#define R4_BI    55680
#define R4_PTR   55808
#define R4_PART  56064
#define RF_BYTES 56576

__global__ __launch_bounds__(128) void k_refine4(
    const float* __restrict__ p_im, const float* __restrict__ bphi)
{
    extern __shared__ __align__(16) char rsp[];
    const uint32_t sb = smem_u32(rsp);
    const int tid = threadIdx.x;
    const int w = tid >> 5, lane = tid & 31;
    const int rg = w >> 1, cg = w & 1;
    const int N = g_ncand;
    const int base = blockIdx.x * 32;
    if (base >= N) return;

    float* sBias = (float*)(rsp + R4_BIAS);
    int* sGI = (int*)(rsp + R4_GI);
    int* sBI = (int*)(rsp + R4_BI);
    const float** sPtr = (const float**)(rsp + R4_PTR);
    float (*sPart)[4] = (float(*)[4])(rsp + R4_PART);

    if (tid < 64) sBias[tid] = bphi[tid];
    if (tid < 32) {
        int e = min(base + tid, N - 1);
        int rowid = g_list_row[e];
        sGI[tid] = g_list_gi[e];
        sBI[tid] = rowid >> 6;
        sPtr[tid] = p_im + (size_t)rowid * D_SZ;
    }
    __syncthreads();

    float4 ar[4];
    uint2 bh[8], bl[8];
#define R4_LOAD(t) do {                                                         \
    _Pragma("unroll")                                                           \
    for (int i = 0; i < 4; i++) {                                               \
        int l = tid + 128 * i; int row = l >> 4, c4 = l & 15;                   \
        ar[i] = *(const float4*)(sPtr[row] + (t) * KC + c4 * 4);                \
    }                                                                           \
    _Pragma("unroll")                                                           \
    for (int i = 0; i < 8; i++) {                                               \
        int l = tid + 128 * i; int row = l >> 4, u = l & 15;                    \
        bh[i] = *(const uint2*)(g_BphHi + row * D_SZ + (t) * KC + u * 4);       \
        bl[i] = *(const uint2*)(g_BphLo + row * D_SZ + (t) * KC + u * 4);       \
    } } while (0)
#define R4_STS(buf) do {                                                        \
    _Pragma("unroll")                                                           \
    for (int i = 0; i < 4; i++) {                                               \
        int l = tid + 128 * i; int row = l >> 4, c4 = l & 15;                   \
        float4 v = ar[i];                                                       \
        float l0, l1, l2, l3;                                                   \
        uint32_t h01 = pack_hi(v.x, v.y, l0, l1);                               \
        uint32_t h23 = pack_hi(v.z, v.w, l2, l3);                               \
        uint32_t q01 = pack_bf(l0, l1);                                         \
        uint32_t q23 = pack_bf(l2, l3);                                         \
        uint32_t off = (uint32_t)((buf) * 4608 + row * 144 + c4 * 8);           \
        *(uint2*)(rsp + R4_AHI + off) = make_uint2(h01, h23);                   \
        *(uint2*)(rsp + R4_ALO + off) = make_uint2(q01, q23);                   \
    }                                                                           \
    _Pragma("unroll")                                                           \
    for (int i = 0; i < 8; i++) {                                               \
        int l = tid + 128 * i; int row = l >> 4, u = l & 15;                    \
        uint32_t off = (uint32_t)((buf) * 9216 + row * 144 + u * 8);            \
        *(uint2*)(rsp + R4_BHI + off) = bh[i];                                  \
        *(uint2*)(rsp + R4_BLO + off) = bl[i];                                  \
    } } while (0)

    R4_LOAD(0);
    R4_STS(0);
    __syncthreads();
    R4_LOAD(1);

    float acc[4][4];
#pragma unroll
    for (int j = 0; j < 4; j++)
#pragma unroll
        for (int q = 0; q < 4; q++) acc[j][q] = 0.f;

    const int m8  = lane & 7;
    const int grp = lane >> 3;
    const uint32_t aoffBase = (uint32_t)((rg * 16 + (grp & 1) * 8 + m8) * 144
                                         + ((grp >> 1) * 8) * 2);
    const uint32_t bbase = (uint32_t)((cg * 32 + (grp >> 1) * 8 + m8) * 144
                                      + (grp & 1) * 16);

#pragma unroll 1
    for (int t = 0; t < NCHUNK; t++) {
        const uint32_t abufH = sb + R4_AHI + (uint32_t)((t & 1) * 4608);
        const uint32_t abufL = sb + R4_ALO + (uint32_t)((t & 1) * 4608);
        const uint32_t bbufH = sb + R4_BHI + (uint32_t)((t & 1) * 9216);
        const uint32_t bbufL = sb + R4_BLO + (uint32_t)((t & 1) * 9216);
#pragma unroll
        for (int ks = 0; ks < 4; ks++) {
            uint32_t ah[4], al[4];
            uint32_t aoff = aoffBase + (uint32_t)(ks * 32);
            LDSM4(ah, abufH + aoff);
            LDSM4(al, abufL + aoff);
#pragma unroll
            for (int tp = 0; tp < 2; tp++) {
                uint32_t bhr[4], blr[4];
                uint32_t boff = bbase + (uint32_t)(tp * 16 * 144 + ks * 32);
                LDSM4(bhr, bbufH + boff);
                LDSM4(blr, bbufL + boff);
                MMA16816(acc[2 * tp],     ah, bhr[0], bhr[1]);
                MMA16816(acc[2 * tp + 1], ah, bhr[2], bhr[3]);
                MMA16816(acc[2 * tp],     ah, blr[0], blr[1]);
                MMA16816(acc[2 * tp + 1], ah, blr[2], blr[3]);
                MMA16816(acc[2 * tp],     al, bhr[0], bhr[1]);
                MMA16816(acc[2 * tp + 1], al, bhr[2], bhr[3]);
            }
        }
        if (t + 1 < NCHUNK) {
            R4_STS((t + 1) & 1);
            if (t + 2 < NCHUNK) R4_LOAD(t + 2);
        }
        __syncthreads();
    }

    const int qr = lane >> 2, qc = lane & 3;
#pragma unroll
    for (int h = 0; h < 2; h++) {
        const int row = rg * 16 + h * 8 + qr;
        const float* xf = g_Xf + (size_t)sBI[row] * 64;
        float n2 = 0.f, dp = 0.f;
#pragma unroll
        for (int j = 0; j < 4; j++) {
            int c = cg * 32 + j * 8 + qc * 2;
            float v0 = acc[j][h * 2 + 0] + sBias[c];
            float v1 = acc[j][h * 2 + 1] + sBias[c + 1];
            n2 = fmaf(v0, v0, n2); n2 = fmaf(v1, v1, n2);
            dp = fmaf(xf[c], v0, dp); dp = fmaf(xf[c + 1], v1, dp);
        }
        n2 += __shfl_xor_sync(0xffffffffu, n2, 1);
        n2 += __shfl_xor_sync(0xffffffffu, n2, 2);
        dp += __shfl_xor_sync(0xffffffffu, dp, 1);
        dp += __shfl_xor_sync(0xffffffffu, dp, 2);
        if (qc == 0) { sPart[row][cg * 2] = n2; sPart[row][cg * 2 + 1] = dp; }
    }
    __syncthreads();
    if (tid < 32 && base + tid < N) {
        float n2 = sPart[tid][0] + sPart[tid][2];
        float dp = sPart[tid][1] + sPart[tid][3];
        g_rs[sGI[tid]] = dp / fmaxf(sqrtf(n2), 1e-12f);
    }
}

// ================= K3: float4 output kernel ===============================
__global__ __launch_bounds__(64) void k_output(
    const float* __restrict__ x, const float* __restrict__ p,
    const float* __restrict__ Wg, const float* __restrict__ bg,
    const float* __restrict__ Wo, const float* __restrict__ bo,
    const float* __restrict__ sig_scale, const float* __restrict__ sig_shift,
    float* __restrict__ out)
{
    __shared__ float wsm[CAP];
    __shared__ int   kk[CAP];
    __shared__ int   s_cnt;
    __shared__ float s_sw;
    const int b = blockIdx.x, tid = threadIdx.x;

    // hoist x loads (float4) above softmax prep
    const float4* xb4 = (const float4*)(x + (size_t)b * D_SZ);
    float4 xv0 = xb4[tid], xv1 = xb4[tid + 64], xv2 = xb4[tid + 128];

    if (tid < 32) {
        const int cnt = g_ccnt[b];
        float s = (tid < cnt) ? g_rs[b * CAP + tid] : -1e30f;
        float m = s;
#pragma unroll
        for (int o = 16; o; o >>= 1)
            m = fmaxf(m, __shfl_xor_sync(0xffffffffu, m, o));
        float e = (tid < cnt) ? expf(1048576.0f * (s - m)) : 0.f;
        float sum = e;
#pragma unroll
        for (int o = 16; o; o >>= 1)
            sum += __shfl_xor_sync(0xffffffffu, sum, o);
        if (tid < cnt) {
            wsm[tid] = e / sum;
            kk[tid]  = g_cand[b * CAP + tid];
        }
        if (tid == 0) {
            s_cnt = cnt;
            float z = m * sig_scale[0] + sig_shift[0];
            s_sw = 1.0f / (1.0f + expf(-z));
        }
    }
    __syncthreads();

    const int cnt = s_cnt;
    const float sw = s_sw;
    float4 a0 = make_float4(0.f, 0.f, 0.f, 0.f), a1 = a0, a2 = a0;
    const float* pb = p + (size_t)b * K_SZ * D_SZ;
    for (int i = 0; i < cnt; i++) {
        float wk = wsm[i];
        if (wk > 1e-12f) {
            const float4* pr4 = (const float4*)(pb + kk[i] * D_SZ);
            float4 p0 = pr4[tid], p1 = pr4[tid + 64], p2 = pr4[tid + 128];
            a0.x = fmaf(wk, p0.x, a0.x); a0.y = fmaf(wk, p0.y, a0.y);
            a0.z = fmaf(wk, p0.z, a0.z); a0.w = fmaf(wk, p0.w, a0.w);
            a1.x = fmaf(wk, p1.x, a1.x); a1.y = fmaf(wk, p1.y, a1.y);
            a1.z = fmaf(wk, p1.z, a1.z); a1.w = fmaf(wk, p1.w, a1.w);
            a2.x = fmaf(wk, p2.x, a2.x); a2.y = fmaf(wk, p2.y, a2.y);
            a2.z = fmaf(wk, p2.z, a2.z); a2.w = fmaf(wk, p2.w, a2.w);
        }
    }

    float g00 = Wg[0], g01 = Wg[1], g02 = Wg[2];
    float g10 = Wg[3], g11 = Wg[4], g12 = Wg[5];
    float g20 = Wg[6], g21 = Wg[7], g22 = Wg[8];
    float bg0 = bg[0], bg1 = bg[1], bg2 = bg[2];
    float o00 = Wo[0], o01 = Wo[1], o02 = Wo[2];
    float o10 = Wo[3], o11 = Wo[4], o12 = Wo[5];
    float o20 = Wo[6], o21 = Wo[7], o22 = Wo[8];
    float bo0 = bo[0], bo1 = bo[1], bo2 = bo[2];

    float4* ob4 = (float4*)(out + (size_t)b * D_SZ);
#define MIX_STORE(comp)                                                          \
    do {                                                                         \
        float m0 = g00 * a0.comp + g01 * a1.comp + g02 * a2.comp + bg0;          \
        float m1 = g10 * a0.comp + g11 * a1.comp + g12 * a2.comp + bg1;          \
        float m2 = g20 * a0.comp + g21 * a1.comp + g22 * a2.comp + bg2;          \
        r0.comp = xv0.comp * (1.0f - sw) + (o00*m0 + o01*m1 + o02*m2 + bo0) * sw;\
        r1.comp = xv1.comp * (1.0f - sw) + (o10*m0 + o11*m1 + o12*m2 + bo1) * sw;\
        r2.comp = xv2.comp * (1.0f - sw) + (o20*m0 + o21*m1 + o22*m2 + bo2) * sw;\
    } while (0)
    float4 r0, r1, r2;
    MIX_STORE(x); MIX_STORE(y); MIX_STORE(z); MIX_STORE(w);
    ob4[tid] = r0; ob4[tid + 64] = r1; ob4[tid + 128] = r2;
}

// ---------------- launch ----------------
extern "C" void kernel_launch(void* const* d_in, const int* in_sizes, int n_in,
                              void* d_out, int out_size) {
    const float* x         = (const float*)d_in[0];
    const float* p         = (const float*)d_in[1];
    const float* x_im      = (const float*)d_in[2];
    const float* p_im      = (const float*)d_in[3];
    const float* Wtheta    = (const float*)d_in[4];
    const float* btheta    = (const float*)d_in[5];
    const float* Wphi      = (const float*)d_in[6];
    const float* bphi      = (const float*)d_in[7];
    const float* Wg        = (const float*)d_in[8];
    const float* bg        = (const float*)d_in[9];
    const float* Wo        = (const float*)d_in[10];
    const float* bo        = (const float*)d_in[11];
    const float* sig_scale = (const float*)d_in[12];
    const float* sig_shift = (const float*)d_in[13];
    float* out = (float*)d_out;

    static int s_attr_done = 0;
    if (!s_attr_done) {
        cudaFuncSetAttribute(k_feat, cudaFuncAttributeMaxDynamicSharedMemorySize,
                             SMEM_BYTES);
        cudaFuncSetAttribute(k_refine4, cudaFuncAttributeMaxDynamicSharedMemorySize,
                             RF_BYTES);
        s_attr_done = 1;
    }

    k_prep<<<(F_SZ * D_SZ + 255) / 256, 256>>>(Wtheta, Wphi);
    k_feat<<<B_SZ / 128, 256, SMEM_BYTES>>>(x_im, btheta);        // x_feat
    k_score3<<<B_SZ, 256>>>(p_im, bphi);                          // cheap + cands
    k_refine4<<<LISTMAX / 32, 128, RF_BYTES>>>(p_im, bphi);       // exact refine
    k_output<<<B_SZ, 64>>>(x, p, Wg, bg, Wo, bo, sig_scale, sig_shift, out);
}

// round 15
// speedup vs baseline: 1.7679x; 1.0570x over previous
#include <cuda_runtime.h>
#include <cuda_bf16.h>
#include <cstdint>

#define B_SZ 2048
#define K_SZ 64
#define D_SZ 768      // C*E*E
#define F_SZ 64       // CF_FEAT
#define KC   64       // k elements per chunk
#define NCHUNK (D_SZ / KC)   // 12
#define CAP  16       // max candidates per b
#define DELTA 0.006f  // candidate margin
#define LISTMAX (B_SZ * CAP)

// ---------------- device scratch ----------------
__device__ float g_Xf[B_SZ * F_SZ];
__device__ int   g_cand[B_SZ * CAP];
__device__ int   g_ccnt[B_SZ];
__device__ float g_rs[B_SZ * CAP];
__device__ int   g_ncand;
__device__ int   g_list_gi[LISTMAX];
__device__ int   g_list_row[LISTMAX];
__device__ __align__(16) __nv_bfloat16 g_BphHi[F_SZ * D_SZ];
__device__ __align__(16) __nv_bfloat16 g_BphLo[F_SZ * D_SZ];
__device__ __align__(16) __nv_bfloat16 g_BthHi[F_SZ * D_SZ];
__device__ __align__(16) __nv_bfloat16 g_BthLo[F_SZ * D_SZ];

// ---------------- helpers ----------------
__device__ __forceinline__ uint32_t smem_u32(const void* p) {
    uint32_t a;
    asm("{ .reg .u64 t; cvta.to.shared.u64 t, %1; cvt.u32.u64 %0, t; }"
        : "=r"(a) : "l"(p));
    return a;
}
#define LDSM4(r, addr) \
    asm volatile("ldmatrix.sync.aligned.m8n8.x4.shared.b16 {%0,%1,%2,%3}, [%4];" \
        : "=r"((r)[0]), "=r"((r)[1]), "=r"((r)[2]), "=r"((r)[3]) : "r"(addr))
#define MMA16816(c, a, b0, b1) \
    asm volatile("mma.sync.aligned.m16n8k16.row.col.f32.bf16.bf16.f32 " \
        "{%0,%1,%2,%3}, {%4,%5,%6,%7}, {%8,%9}, {%0,%1,%2,%3};" \
        : "+f"((c)[0]), "+f"((c)[1]), "+f"((c)[2]), "+f"((c)[3]) \
        : "r"((a)[0]), "r"((a)[1]), "r"((a)[2]), "r"((a)[3]), "r"(b0), "r"(b1))
#define CP_ASYNC8(dst, src) \
    asm volatile("cp.async.ca.shared.global [%0], [%1], 8;" \
        :: "r"(dst), "l"(src) : "memory")
#define CP_COMMIT() asm volatile("cp.async.commit_group;" ::: "memory")
#define CP_WAIT0()  asm volatile("cp.async.wait_group 0;" ::: "memory")

__device__ __forceinline__ uint32_t pack2(float x, float y) {
    __nv_bfloat162 t = __float22bfloat162_rn(make_float2(x, y));
    return *reinterpret_cast<uint32_t*>(&t);
}
__device__ __forceinline__ uint32_t pack_hi(float x, float y,
                                            float& lx, float& ly) {
    __nv_bfloat16 hx = __float2bfloat16(x), hy = __float2bfloat16(y);
    lx = x - __bfloat162float(hx);
    ly = y - __bfloat162float(hy);
    return ((uint32_t)__bfloat16_as_ushort(hy) << 16) | __bfloat16_as_ushort(hx);
}

// ---------------- K0: split W's into bf16 hi/lo + reset counter ------------
__global__ void k_prep(const float* __restrict__ Wth, const float* __restrict__ Wph) {
    int i = blockIdx.x * 256 + threadIdx.x;
    if (i == 0) g_ncand = 0;
    if (i < F_SZ * D_SZ) {
        float a = Wph[i];
        __nv_bfloat16 h = __float2bfloat16(a);
        g_BphHi[i] = h;
        g_BphLo[i] = __float2bfloat16(a - __bfloat162float(h));
        float b = Wth[i];
        __nv_bfloat16 g = __float2bfloat16(b);
        g_BthHi[i] = g;
        g_BthLo[i] = __float2bfloat16(b - __bfloat162float(g));
    }
}

// ================= x_feat: 16 rows/CTA, 128 CTAs, 3-pass ==================
__global__ __launch_bounds__(128) void k_feat2(const float* __restrict__ x_im,
                                               const float* __restrict__ btheta) {
    __shared__ __align__(16) char sAhi[16 * 144];
    __shared__ __align__(16) char sAlo[16 * 144];
    __shared__ __align__(16) char sBhi[64 * 144];
    __shared__ __align__(16) char sBlo[64 * 144];
    __shared__ float sBias[64];
    __shared__ float sPartN[16][4];
    __shared__ float sInv[16];

    const uint32_t sbAh = smem_u32(sAhi), sbAl = smem_u32(sAlo);
    const uint32_t sbBh = smem_u32(sBhi), sbBl = smem_u32(sBlo);
    const int tid = threadIdx.x;
    const int w = tid >> 5, lane = tid & 31;
    const int cg = w;
    const int m8 = lane & 7, grp = lane >> 3;
    const int qr = lane >> 2, qc = lane & 3;

    if (tid < 64) sBias[tid] = btheta[tid];

    const float* Ab = x_im + (size_t)blockIdx.x * 16 * D_SZ;

    float acc[2][4];
#pragma unroll
    for (int j = 0; j < 2; j++)
#pragma unroll
        for (int q = 0; q < 4; q++) acc[j][q] = 0.f;

    const uint32_t aoffBase = (uint32_t)(((grp & 1) * 8 + m8) * 144
                                         + ((grp >> 1) * 8) * 2);
    const uint32_t bbase = (uint32_t)((cg * 16 + (grp >> 1) * 8 + m8) * 144
                                      + (grp & 1) * 16);

#pragma unroll 1
    for (int t = 0; t < NCHUNK; t++) {
#pragma unroll
        for (int i = 0; i < 2; i++) {
            int l = tid + 128 * i; int row = l >> 4, c4 = l & 15;
            float4 v = *(const float4*)(Ab + row * D_SZ + t * KC + c4 * 4);
            float l0, l1, l2, l3;
            uint32_t h01 = pack_hi(v.x, v.y, l0, l1);
            uint32_t h23 = pack_hi(v.z, v.w, l2, l3);
            uint32_t off = (uint32_t)(row * 144 + c4 * 8);
            *(uint2*)(sAhi + off) = make_uint2(h01, h23);
            *(uint2*)(sAlo + off) = make_uint2(pack2(l0, l1), pack2(l2, l3));
        }
#pragma unroll
        for (int i = 0; i < 8; i++) {
            int l = tid + 128 * i; int row = l >> 4, u = l & 15;
            uint32_t off = (uint32_t)(row * 144 + u * 8);
            *(uint2*)(sBhi + off) = *(const uint2*)(g_BthHi + row * D_SZ + t * KC + u * 4);
            *(uint2*)(sBlo + off) = *(const uint2*)(g_BthLo + row * D_SZ + t * KC + u * 4);
        }
        __syncthreads();
#pragma unroll
        for (int ks = 0; ks < 4; ks++) {
            uint32_t ah[4], al[4], bhr[4], blr[4];
            LDSM4(ah, sbAh + aoffBase + (uint32_t)(ks * 32));
            LDSM4(al, sbAl + aoffBase + (uint32_t)(ks * 32));
            LDSM4(bhr, sbBh + bbase + (uint32_t)(ks * 32));
            LDSM4(blr, sbBl + bbase + (uint32_t)(ks * 32));
            MMA16816(acc[0], ah, bhr[0], bhr[1]);
            MMA16816(acc[1], ah, bhr[2], bhr[3]);
            MMA16816(acc[0], ah, blr[0], blr[1]);
            MMA16816(acc[1], ah, blr[2], blr[3]);
            MMA16816(acc[0], al, bhr[0], bhr[1]);
            MMA16816(acc[1], al, bhr[2], bhr[3]);
        }
        __syncthreads();
    }

    // ---- epilogue: bias + cross-warp norm + store normalized features ----
#pragma unroll
    for (int h = 0; h < 2; h++) {
        const int row = h * 8 + qr;
        float n2 = 0.f;
#pragma unroll
        for (int j = 0; j < 2; j++) {
            int c = cg * 16 + j * 8 + qc * 2;
            float v0 = acc[j][h * 2 + 0] + sBias[c];
            float v1 = acc[j][h * 2 + 1] + sBias[c + 1];
            n2 = fmaf(v0, v0, n2); n2 = fmaf(v1, v1, n2);
        }
        n2 += __shfl_xor_sync(0xffffffffu, n2, 1);
        n2 += __shfl_xor_sync(0xffffffffu, n2, 2);
        if (qc == 0) sPartN[row][cg] = n2;
    }
    __syncthreads();
    if (tid < 16) {
        float n2 = sPartN[tid][0] + sPartN[tid][1] + sPartN[tid][2] + sPartN[tid][3];
        sInv[tid] = 1.0f / fmaxf(sqrtf(n2), 1e-12f);
    }
    __syncthreads();
#pragma unroll
    for (int h = 0; h < 2; h++) {
        const int row = h * 8 + qr;
        float inv = sInv[row];
        float* o = g_Xf + ((size_t)blockIdx.x * 16 + row) * 64;
#pragma unroll
        for (int j = 0; j < 2; j++) {
            int c = cg * 16 + j * 8 + qc * 2;
            o[c]     = (acc[j][h * 2 + 0] + sBias[c]) * inv;
            o[c + 1] = (acc[j][h * 2 + 1] + sBias[c + 1]) * inv;
        }
    }
}

// ================= Stage 1: 64 rows/CTA, cp.async B, 1 sync/chunk ==========
__global__ __launch_bounds__(256) void k_score3(
    const float* __restrict__ p_im, const float* __restrict__ bphi)
{
    __shared__ __align__(16) char sA[2][64 * 144];
    __shared__ __align__(16) char sB[2][64 * 144];
    __shared__ float sXf[64];
    __shared__ float sBias[64];
    __shared__ float sPart[64][4];
    __shared__ float sSc[64];

    const uint32_t sbA = smem_u32(sA), sbB = smem_u32(sB);
    const int tid = threadIdx.x;
    const int w = tid >> 5, lane = tid & 31;
    const int rg = w >> 1, cg = w & 1;
    const int b = blockIdx.x;

    if (tid < 64) {
        sBias[tid] = bphi[tid];
        sXf[tid] = g_Xf[(size_t)b * 64 + tid];
    }

    const float* Ab = p_im + (size_t)b * K_SZ * D_SZ;

    float4 ar[4];
#define S3_LOAD_A(t) do {                                                       \
    _Pragma("unroll")                                                           \
    for (int i = 0; i < 4; i++) {                                               \
        int l = tid + 256 * i; int row = l >> 4, c4 = l & 15;                   \
        ar[i] = *(const float4*)(Ab + row * D_SZ + (t) * KC + c4 * 4);          \
    } } while (0)
#define S3_STS_A(buf) do {                                                      \
    _Pragma("unroll")                                                           \
    for (int i = 0; i < 4; i++) {                                               \
        int l = tid + 256 * i; int row = l >> 4, c4 = l & 15;                   \
        float4 v = ar[i];                                                       \
        uint32_t off = (uint32_t)(row * 144 + c4 * 8);                          \
        *(uint2*)(sA[buf] + off) = make_uint2(pack2(v.x, v.y), pack2(v.z, v.w));\
    } } while (0)
#define S3_CP_B(t, buf) do {                                                    \
    _Pragma("unroll")                                                           \
    for (int i = 0; i < 4; i++) {                                               \
        int l = tid + 256 * i; int row = l >> 4, c4 = l & 15;                   \
        uint32_t dst = sbB + (uint32_t)((buf) * 64 * 144 + row * 144 + c4 * 8); \
        CP_ASYNC8(dst, g_BphHi + row * D_SZ + (t) * KC + c4 * 4);               \
    } CP_COMMIT(); } while (0)

    S3_CP_B(0, 0);
    S3_LOAD_A(0);
    S3_STS_A(0);
    CP_WAIT0();
    __syncthreads();
    S3_LOAD_A(1);

    float acc[4][4];
#pragma unroll
    for (int j = 0; j < 4; j++)
#pragma unroll
        for (int q = 0; q < 4; q++) acc[j][q] = 0.f;

    const int m8  = lane & 7;
    const int grp = lane >> 3;
    const uint32_t aoffBase = (uint32_t)((rg * 16 + (grp & 1) * 8 + m8) * 144
                                         + ((grp >> 1) * 8) * 2);
    const uint32_t bbase = (uint32_t)((cg * 32 + (grp >> 1) * 8 + m8) * 144
                                      + (grp & 1) * 16);

#pragma unroll 1
    for (int t = 0; t < NCHUNK; t++) {
        if (t + 1 < NCHUNK) S3_CP_B(t + 1, (t + 1) & 1);
        const uint32_t abuf = sbA + (uint32_t)((t & 1) * 64 * 144);
        const uint32_t bbuf = sbB + (uint32_t)((t & 1) * 64 * 144);
#pragma unroll
        for (int ks = 0; ks < 4; ks++) {
            uint32_t ah[4];
            LDSM4(ah, abuf + aoffBase + (uint32_t)(ks * 32));
#pragma unroll
            for (int tp = 0; tp < 2; tp++) {
                uint32_t bhr[4];
                LDSM4(bhr, bbuf + bbase + (uint32_t)(tp * 16 * 144 + ks * 32));
                MMA16816(acc[2 * tp],     ah, bhr[0], bhr[1]);
                MMA16816(acc[2 * tp + 1], ah, bhr[2], bhr[3]);
            }
        }
        if (t + 1 < NCHUNK) {
            S3_STS_A((t + 1) & 1);
            if (t + 2 < NCHUNK) S3_LOAD_A(t + 2);
            CP_WAIT0();
        }
        __syncthreads();
    }

    // ---- epilogue: bias + partial norm/dot, cross-warp combine ----
    const int qr = lane >> 2, qc = lane & 3;
#pragma unroll
    for (int h = 0; h < 2; h++) {
        const int row = rg * 16 + h * 8 + qr;
        float n2 = 0.f, dp = 0.f;
#pragma unroll
        for (int j = 0; j < 4; j++) {
            int c = cg * 32 + j * 8 + qc * 2;
            float v0 = acc[j][h * 2 + 0] + sBias[c];
            float v1 = acc[j][h * 2 + 1] + sBias[c + 1];
            n2 = fmaf(v0, v0, n2); n2 = fmaf(v1, v1, n2);
            dp = fmaf(sXf[c], v0, dp); dp = fmaf(sXf[c + 1], v1, dp);
        }
        n2 += __shfl_xor_sync(0xffffffffu, n2, 1);
        n2 += __shfl_xor_sync(0xffffffffu, n2, 2);
        dp += __shfl_xor_sync(0xffffffffu, dp, 1);
        dp += __shfl_xor_sync(0xffffffffu, dp, 2);
        if (qc == 0) { sPart[row][cg * 2] = n2; sPart[row][cg * 2 + 1] = dp; }
    }
    __syncthreads();
    if (tid < 64) {
        float n2 = sPart[tid][0] + sPart[tid][2];
        float dp = sPart[tid][1] + sPart[tid][3];
        sSc[tid] = dp / fmaxf(sqrtf(n2), 1e-12f);
    }
    __syncthreads();

    // ---- candidate selection + push (warp 0) ----
    if (w == 0) {
        float s0 = sSc[lane];
        float s1 = sSc[32 + lane];
        float m = fmaxf(s0, s1);
#pragma unroll
        for (int o = 16; o; o >>= 1)
            m = fmaxf(m, __shfl_xor_sync(0xffffffffu, m, o));
        float thr = m - DELTA;
        unsigned b0m = __ballot_sync(0xffffffffu, s0 > thr);
        unsigned b1m = __ballot_sync(0xffffffffu, s1 > thr);
        int c0 = __popc(b0m);
        int cnt = min(c0 + __popc(b1m), CAP);
        unsigned lt = (1u << lane) - 1u;
        int gbase = 0;
        if (lane == 0) {
            g_ccnt[b] = cnt;
            gbase = atomicAdd(&g_ncand, cnt);
        }
        gbase = __shfl_sync(0xffffffffu, gbase, 0);
        if (s0 > thr) {
            int slot = __popc(b0m & lt);
            if (slot < CAP) {
                g_cand[b * CAP + slot] = lane;
                g_list_gi[gbase + slot] = b * CAP + slot;
                g_list_row[gbase + slot] = b * K_SZ + lane;
            }
        }
        if (s1 > thr) {
            int slot = c0 + __popc(b1m & lt);
            if (slot < CAP) {
                g_cand[b * CAP + slot] = 32 + lane;
                g_list_gi[gbase + slot] = b * CAP + slot;
                g_list_row[gbase + slot] = b * K_SZ + 32 + lane;
            }
        }
    }
}

// ================= Stage 2: 3-pass refine, 16 rows/CTA, double-buffered ====
__global__ __launch_bounds__(128) void k_refine5(
    const float* __restrict__ p_im, const float* __restrict__ bphi)
{
    __shared__ __align__(16) char sAhi[2][16 * 144];
    __shared__ __align__(16) char sAlo[2][16 * 144];
    __shared__ __align__(16) char sBhi[2][64 * 144];
    __shared__ __align__(16) char sBlo[2][64 * 144];
    __shared__ float sBias[64];
    __shared__ int   sGI[16];
    __shared__ int   sBI[16];
    __shared__ const float* sPtr[16];
    __shared__ float sPart[16][4][2];

    const uint32_t sbAh = smem_u32(sAhi), sbAl = smem_u32(sAlo);
    const uint32_t sbBh = smem_u32(sBhi), sbBl = smem_u32(sBlo);
    const int tid = threadIdx.x;
    const int w = tid >> 5, lane = tid & 31;
    const int cg = w;
    const int N = g_ncand;
    const int base = blockIdx.x * 16;
    if (base >= N) return;

    if (tid < 64) sBias[tid] = bphi[tid];
    if (tid < 16) {
        int e = min(base + tid, N - 1);
        int rowid = g_list_row[e];
        sGI[tid] = g_list_gi[e];
        sBI[tid] = rowid >> 6;
        sPtr[tid] = p_im + (size_t)rowid * D_SZ;
    }
    __syncthreads();

    float4 ar[2];
    uint2 bh[8], bl[8];
#define R5_LOAD(t) do {                                                         \
    _Pragma("unroll")                                                           \
    for (int i = 0; i < 2; i++) {                                               \
        int l = tid + 128 * i; int row = l >> 4, c4 = l & 15;                   \
        ar[i] = *(const float4*)(sPtr[row] + (t) * KC + c4 * 4);                \
    }                                                                           \
    _Pragma("unroll")                                                           \
    for (int i = 0; i < 8; i++) {                                               \
        int l = tid + 128 * i; int row = l >> 4, u = l & 15;                    \
        bh[i] = *(const uint2*)(g_BphHi + row * D_SZ + (t) * KC + u * 4);       \
        bl[i] = *(const uint2*)(g_BphLo + row * D_SZ + (t) * KC + u * 4);       \
    } } while (0)
#define R5_STS(buf) do {                                                        \
    _Pragma("unroll")                                                           \
    for (int i = 0; i < 2; i++) {                                               \
        int l = tid + 128 * i; int row = l >> 4, c4 = l & 15;                   \
        float4 v = ar[i];                                                       \
        float l0, l1, l2, l3;                                                   \
        uint32_t h01 = pack_hi(v.x, v.y, l0, l1);                               \
        uint32_t h23 = pack_hi(v.z, v.w, l2, l3);                               \
        uint32_t off = (uint32_t)(row * 144 + c4 * 8);                          \
        *(uint2*)(sAhi[buf] + off) = make_uint2(h01, h23);                      \
        *(uint2*)(sAlo[buf] + off) = make_uint2(pack2(l0, l1), pack2(l2, l3));  \
    }                                                                           \
    _Pragma("unroll")                                                           \
    for (int i = 0; i < 8; i++) {                                               \
        int l = tid + 128 * i; int row = l >> 4, u = l & 15;                    \
        uint32_t off = (uint32_t)(row * 144 + u * 8);                           \
        *(uint2*)(sBhi[buf] + off) = bh[i];                                     \
        *(uint2*)(sBlo[buf] + off) = bl[i];                                     \
    } } while (0)

    R5_LOAD(0);
    R5_STS(0);
    __syncthreads();
    R5_LOAD(1);

    float acc[2][4];
#pragma unroll
    for (int j = 0; j < 2; j++)
#pragma unroll
        for (int q = 0; q < 4; q++) acc[j][q] = 0.f;

    const int m8  = lane & 7;
    const int grp = lane >> 3;
    const uint32_t aoffBase = (uint32_t)(((grp & 1) * 8 + m8) * 144
                                         + ((grp >> 1) * 8) * 2);
    const uint32_t bbase = (uint32_t)((cg * 16 + (grp >> 1) * 8 + m8) * 144
                                      + (grp & 1) * 16);

#pragma unroll 1
    for (int t = 0; t < NCHUNK; t++) {
        const uint32_t aH = sbAh + (uint32_t)((t & 1) * 16 * 144);
        const uint32_t aL = sbAl + (uint32_t)((t & 1) * 16 * 144);
        const uint32_t bH = sbBh + (uint32_t)((t & 1) * 64 * 144);
        const uint32_t bL = sbBl + (uint32_t)((t & 1) * 64 * 144);
#pragma unroll
        for (int ks = 0; ks < 4; ks++) {
            uint32_t ah[4], al[4], bhr[4], blr[4];
            LDSM4(ah, aH + aoffBase + (uint32_t)(ks * 32));
            LDSM4(al, aL + aoffBase + (uint32_t)(ks * 32));
            LDSM4(bhr, bH + bbase + (uint32_t)(ks * 32));
            LDSM4(blr, bL + bbase + (uint32_t)(ks * 32));
            MMA16816(acc[0], ah, bhr[0], bhr[1]);
            MMA16816(acc[1], ah, bhr[2], bhr[3]);
            MMA16816(acc[0], ah, blr[0], blr[1]);
            MMA16816(acc[1], ah, blr[2], blr[3]);
            MMA16816(acc[0], al, bhr[0], bhr[1]);
            MMA16816(acc[1], al, bhr[2], bhr[3]);
        }
        if (t + 1 < NCHUNK) {
            R5_STS((t + 1) & 1);
            if (t + 2 < NCHUNK) R5_LOAD(t + 2);
        }
        __syncthreads();
    }

    const int qr = lane >> 2, qc = lane & 3;
#pragma unroll
    for (int h = 0; h < 2; h++) {
        const int row = h * 8 + qr;
        const float* xf = g_Xf + (size_t)sBI[row] * 64;
        float n2 = 0.f, dp = 0.f;
#pragma unroll
        for (int j = 0; j < 2; j++) {
            int c = cg * 16 + j * 8 + qc * 2;
            float v0 = acc[j][h * 2 + 0] + sBias[c];
            float v1 = acc[j][h * 2 + 1] + sBias[c + 1];
            n2 = fmaf(v0, v0, n2); n2 = fmaf(v1, v1, n2);
            dp = fmaf(xf[c], v0, dp); dp = fmaf(xf[c + 1], v1, dp);
        }
        n2 += __shfl_xor_sync(0xffffffffu, n2, 1);
        n2 += __shfl_xor_sync(0xffffffffu, n2, 2);
        dp += __shfl_xor_sync(0xffffffffu, dp, 1);
        dp += __shfl_xor_sync(0xffffffffu, dp, 2);
        if (qc == 0) { sPart[row][cg][0] = n2; sPart[row][cg][1] = dp; }
    }
    __syncthreads();
    if (tid < 16 && base + tid < N) {
        float n2 = sPart[tid][0][0] + sPart[tid][1][0]
                 + sPart[tid][2][0] + sPart[tid][3][0];
        float dp = sPart[tid][0][1] + sPart[tid][1][1]
                 + sPart[tid][2][1] + sPart[tid][3][1];
        g_rs[sGI[tid]] = dp / fmaxf(sqrtf(n2), 1e-12f);
    }
}

// ================= K3: float4 output kernel ===============================
__global__ __launch_bounds__(64) void k_output(
    const float* __restrict__ x, const float* __restrict__ p,
    const float* __restrict__ Wg, const float* __restrict__ bg,
    const float* __restrict__ Wo, const float* __restrict__ bo,
    const float* __restrict__ sig_scale, const float* __restrict__ sig_shift,
    float* __restrict__ out)
{
    __shared__ float wsm[CAP];
    __shared__ int   kk[CAP];
    __shared__ int   s_cnt;
    __shared__ float s_sw;
    const int b = blockIdx.x, tid = threadIdx.x;

    const float4* xb4 = (const float4*)(x + (size_t)b * D_SZ);
    float4 xv0 = xb4[tid], xv1 = xb4[tid + 64], xv2 = xb4[tid + 128];

    if (tid < 32) {
        const int cnt = g_ccnt[b];
        float s = (tid < cnt) ? g_rs[b * CAP + tid] : -1e30f;
        float m = s;
#pragma unroll
        for (int o = 16; o; o >>= 1)
            m = fmaxf(m, __shfl_xor_sync(0xffffffffu, m, o));
        float e = (tid < cnt) ? expf(1048576.0f * (s - m)) : 0.f;
        float sum = e;
#pragma unroll
        for (int o = 16; o; o >>= 1)
            sum += __shfl_xor_sync(0xffffffffu, sum, o);
        if (tid < cnt) {
            wsm[tid] = e / sum;
            kk[tid]  = g_cand[b * CAP + tid];
        }
        if (tid == 0) {
            s_cnt = cnt;
            float z = m * sig_scale[0] + sig_shift[0];
            s_sw = 1.0f / (1.0f + expf(-z));
        }
    }
    __syncthreads();

    const int cnt = s_cnt;
    const float sw = s_sw;
    float4 a0 = make_float4(0.f, 0.f, 0.f, 0.f), a1 = a0, a2 = a0;
    const float* pb = p + (size_t)b * K_SZ * D_SZ;
    for (int i = 0; i < cnt; i++) {
        float wk = wsm[i];
        if (wk > 1e-12f) {
            const float4* pr4 = (const float4*)(pb + kk[i] * D_SZ);
            float4 p0 = pr4[tid], p1 = pr4[tid + 64], p2 = pr4[tid + 128];
            a0.x = fmaf(wk, p0.x, a0.x); a0.y = fmaf(wk, p0.y, a0.y);
            a0.z = fmaf(wk, p0.z, a0.z); a0.w = fmaf(wk, p0.w, a0.w);
            a1.x = fmaf(wk, p1.x, a1.x); a1.y = fmaf(wk, p1.y, a1.y);
            a1.z = fmaf(wk, p1.z, a1.z); a1.w = fmaf(wk, p1.w, a1.w);
            a2.x = fmaf(wk, p2.x, a2.x); a2.y = fmaf(wk, p2.y, a2.y);
            a2.z = fmaf(wk, p2.z, a2.z); a2.w = fmaf(wk, p2.w, a2.w);
        }
    }

    float g00 = Wg[0], g01 = Wg[1], g02 = Wg[2];
    float g10 = Wg[3], g11 = Wg[4], g12 = Wg[5];
    float g20 = Wg[6], g21 = Wg[7], g22 = Wg[8];
    float bg0 = bg[0], bg1 = bg[1], bg2 = bg[2];
    float o00 = Wo[0], o01 = Wo[1], o02 = Wo[2];
    float o10 = Wo[3], o11 = Wo[4], o12 = Wo[5];
    float o20 = Wo[6], o21 = Wo[7], o22 = Wo[8];
    float bo0 = bo[0], bo1 = bo[1], bo2 = bo[2];

    float4* ob4 = (float4*)(out + (size_t)b * D_SZ);
#define MIX_STORE(comp)                                                          \
    do {                                                                         \
        float m0 = g00 * a0.comp + g01 * a1.comp + g02 * a2.comp + bg0;          \
        float m1 = g10 * a0.comp + g11 * a1.comp + g12 * a2.comp + bg1;          \
        float m2 = g20 * a0.comp + g21 * a1.comp + g22 * a2.comp + bg2;          \
        r0.comp = xv0.comp * (1.0f - sw) + (o00*m0 + o01*m1 + o02*m2 + bo0) * sw;\
        r1.comp = xv1.comp * (1.0f - sw) + (o10*m0 + o11*m1 + o12*m2 + bo1) * sw;\
        r2.comp = xv2.comp * (1.0f - sw) + (o20*m0 + o21*m1 + o22*m2 + bo2) * sw;\
    } while (0)
    float4 r0, r1, r2;
    MIX_STORE(x); MIX_STORE(y); MIX_STORE(z); MIX_STORE(w);
    ob4[tid] = r0; ob4[tid + 64] = r1; ob4[tid + 128] = r2;
}

// ---------------- launch ----------------
extern "C" void kernel_launch(void* const* d_in, const int* in_sizes, int n_in,
                              void* d_out, int out_size) {
    const float* x         = (const float*)d_in[0];
    const float* p         = (const float*)d_in[1];
    const float* x_im      = (const float*)d_in[2];
    const float* p_im      = (const float*)d_in[3];
    const float* Wtheta    = (const float*)d_in[4];
    const float* btheta    = (const float*)d_in[5];
    const float* Wphi      = (const float*)d_in[6];
    const float* bphi      = (const float*)d_in[7];
    const float* Wg        = (const float*)d_in[8];
    const float* bg        = (const float*)d_in[9];
    const float* Wo        = (const float*)d_in[10];
    const float* bo        = (const float*)d_in[11];
    const float* sig_scale = (const float*)d_in[12];
    const float* sig_shift = (const float*)d_in[13];
    float* out = (float*)d_out;

    k_prep<<<(F_SZ * D_SZ + 255) / 256, 256>>>(Wtheta, Wphi);
    k_feat2<<<B_SZ / 16, 128>>>(x_im, btheta);                    // x_feat
    k_score3<<<B_SZ, 256>>>(p_im, bphi);                          // cheap + cands
    k_refine5<<<LISTMAX / 16, 128>>>(p_im, bphi);                 // exact refine
    k_output<<<B_SZ, 64>>>(x, p, Wg, bg, Wo, bo, sig_scale, sig_shift, out);
}